// round 1
// baseline (speedup 1.0000x reference)
#include <cuda_runtime.h>
#include <cuda_bf16.h>
#include <math.h>

// ---------------------------------------------------------------------------
// ChannelBlock: B=32, N=784 (28x28), C=384, heads=8, hd=48, MLP hidden=1536
// Pipeline:
//   xa  = cpe0(x)                      depthwise 3x3 + residual
//   ln1 = LN(xa)
//   qkv = ln1 @ qkv_w^T                (25088 x 1152)
//   attn= softmax((k*s)^T v) per (b,h) 48x48
//   att = q @ attn^T  -> (B,N,C)
//   xb  = xa + att @ proj_w^T + proj_b
//   xc  = cpe1(xb)                     (stored back into g_xa)
//   ln2 = LN(xc)
//   h   = gelu(ln2 @ fc1^T + b1)
//   out = xc + h @ fc2^T + b2
// ---------------------------------------------------------------------------

#define Bsz   32
#define Ntok  784
#define Cdim  384
#define NT    (Bsz * Ntok)     // 25088
#define H3    (3 * Cdim)       // 1152
#define HID   1536
#define NH    8
#define HD    48

// scratch (static device memory; no allocation anywhere)
__device__ float g_xa  [(size_t)NT * Cdim];
__device__ float g_ln  [(size_t)NT * Cdim];
__device__ float g_qkv [(size_t)NT * H3];
__device__ float g_attn[(size_t)Bsz * NH * HD * HD];
__device__ float g_att [(size_t)NT * Cdim];
__device__ float g_xb  [(size_t)NT * Cdim];
__device__ float g_h   [(size_t)NT * HID];

// ---------------------------------------------------------------------------
// Depthwise 3x3 conv (SAME) + residual.  x layout (B, N, C); weights (C,1,3,3).
// ---------------------------------------------------------------------------
__global__ void cpe_kernel(const float* __restrict__ x,
                           const float* __restrict__ w,
                           const float* __restrict__ bias,
                           float* __restrict__ y)
{
    int c = threadIdx.x;               // 0..383
    int n = blockIdx.x;                // 0..783
    int b = blockIdx.y;                // 0..31
    int i = n / 28, j = n % 28;

    const float* xb = x + (size_t)b * Ntok * Cdim + c;
    float acc = bias[c];
    const float* wc = w + c * 9;
#pragma unroll
    for (int di = -1; di <= 1; di++) {
        int ii = i + di;
        if (ii < 0 || ii >= 28) continue;
#pragma unroll
        for (int dj = -1; dj <= 1; dj++) {
            int jj = j + dj;
            if (jj < 0 || jj >= 28) continue;
            acc += wc[(di + 1) * 3 + (dj + 1)] * xb[(size_t)(ii * 28 + jj) * Cdim];
        }
    }
    size_t idx = ((size_t)b * Ntok + n) * Cdim + c;
    y[idx] = x[idx] + acc;
}

// ---------------------------------------------------------------------------
// LayerNorm over last dim (384). One warp per row, 8 rows per block.
// ---------------------------------------------------------------------------
__global__ void ln_kernel(const float* __restrict__ x,
                          const float* __restrict__ g,
                          const float* __restrict__ b,
                          float* __restrict__ y)
{
    int warp = threadIdx.x >> 5;
    int lane = threadIdx.x & 31;
    int row  = blockIdx.x * 8 + warp;

    const float* xr = x + (size_t)row * Cdim;
    float v[12];
    float s = 0.f, sq = 0.f;
#pragma unroll
    for (int i = 0; i < 12; i++) {
        v[i] = xr[lane + 32 * i];
        s  += v[i];
        sq += v[i] * v[i];
    }
#pragma unroll
    for (int o = 16; o; o >>= 1) {
        s  += __shfl_xor_sync(0xffffffffu, s,  o);
        sq += __shfl_xor_sync(0xffffffffu, sq, o);
    }
    float mean = s * (1.f / Cdim);
    float var  = sq * (1.f / Cdim) - mean * mean;
    float rs   = rsqrtf(var + 1e-5f);

    float* yr = y + (size_t)row * Cdim;
#pragma unroll
    for (int i = 0; i < 12; i++) {
        int c = lane + 32 * i;
        yr[c] = (v[i] - mean) * rs * g[c] + b[c];
    }
}

// ---------------------------------------------------------------------------
// Tiled fp32 GEMM, NT form:  C[m,n] = sum_k A[m,k] * W[n,k]  (+ epilogue)
// BM=BN=128, BK=16, 256 threads, 8x8 register tiles.
// EPI: 0 = none, 2 = +bias then exact GELU, 3 = +bias +residual
// Assumes M%128==0, N%128==0, K%16==0 (true for all calls here).
// ---------------------------------------------------------------------------
#define GBM 128
#define GBN 128
#define GBK 16
#define GPAD 4   // row stride 132 floats = 528B (16B aligned, de-conflicts STS)

template<int EPI>
__global__ __launch_bounds__(256, 2)
void gemm_nt(const float* __restrict__ A, const float* __restrict__ W,
             const float* __restrict__ bias, const float* __restrict__ res,
             float* __restrict__ C, int M, int N, int K)
{
    __shared__ float As[GBK][GBM + GPAD];
    __shared__ float Bs[GBK][GBN + GPAD];

    int tid = threadIdx.x;
    int tx = tid & 15;       // column group
    int ty = tid >> 4;       // row group
    int row0 = blockIdx.y * GBM;
    int col0 = blockIdx.x * GBN;

    const float* Ab = A + (size_t)row0 * K;
    const float* Wb = W + (size_t)col0 * K;

    float acc[8][8];
#pragma unroll
    for (int i = 0; i < 8; i++)
#pragma unroll
        for (int j = 0; j < 8; j++) acc[i][j] = 0.f;

    for (int kt = 0; kt < K; kt += GBK) {
#pragma unroll
        for (int i = 0; i < 8; i++) {
            int idx = tid + i * 256;         // 0..2047
            int m = idx >> 4;                // 0..127
            int k = idx & 15;                // 0..15
            As[k][m] = Ab[(size_t)m * K + kt + k];
            Bs[k][m] = Wb[(size_t)m * K + kt + k];
        }
        __syncthreads();

#pragma unroll
        for (int k = 0; k < GBK; k++) {
            float ra[8], rb[8];
            float4 a0 = *(const float4*)&As[k][ty * 8];
            float4 a1 = *(const float4*)&As[k][ty * 8 + 4];
            float4 b0 = *(const float4*)&Bs[k][tx * 8];
            float4 b1 = *(const float4*)&Bs[k][tx * 8 + 4];
            ra[0]=a0.x; ra[1]=a0.y; ra[2]=a0.z; ra[3]=a0.w;
            ra[4]=a1.x; ra[5]=a1.y; ra[6]=a1.z; ra[7]=a1.w;
            rb[0]=b0.x; rb[1]=b0.y; rb[2]=b0.z; rb[3]=b0.w;
            rb[4]=b1.x; rb[5]=b1.y; rb[6]=b1.z; rb[7]=b1.w;
#pragma unroll
            for (int i = 0; i < 8; i++)
#pragma unroll
                for (int j = 0; j < 8; j++)
                    acc[i][j] = fmaf(ra[i], rb[j], acc[i][j]);
        }
        __syncthreads();
    }

#pragma unroll
    for (int i = 0; i < 8; i++) {
        int row = row0 + ty * 8 + i;
#pragma unroll
        for (int j = 0; j < 8; j++) {
            int col = col0 + tx * 8 + j;
            size_t idx = (size_t)row * N + col;
            float v = acc[i][j];
            if (EPI == 2) {
                v += bias[col];
                v = 0.5f * v * (1.f + erff(v * 0.7071067811865475f));
            } else if (EPI == 3) {
                v += bias[col] + res[idx];
            }
            C[idx] = v;
        }
    }
}

// ---------------------------------------------------------------------------
// Channel attention, stage A: attn[b,h] = softmax_e( (k*s)^T v )  -> 48x48
// One block per (b,h). 256 threads, each owns a 3x3 tile of the 48x48 output.
// ---------------------------------------------------------------------------
__global__ __launch_bounds__(256)
void attnA_kernel(const float* __restrict__ qkv, float* __restrict__ attn_out)
{
    __shared__ float ks[32][49];
    __shared__ float vs[32][49];
    __shared__ float at[48][49];

    int bh = blockIdx.x;
    int b = bh >> 3, h = bh & 7;
    int tid = threadIdx.x;
    int tx = tid & 15, ty = tid >> 4;
    const float scale = 0.14433756729740643f;   // 48^-0.5

    float acc[3][3] = {{0.f,0.f,0.f},{0.f,0.f,0.f},{0.f,0.f,0.f}};
    const float* base = qkv + (size_t)b * Ntok * H3 + h * HD;

    for (int n0 = 0; n0 < Ntok; n0 += 32) {
        int cnt = min(32, Ntok - n0);
        for (int idx = tid; idx < cnt * HD; idx += 256) {
            int nn = idx / HD, d = idx % HD;
            const float* r = base + (size_t)(n0 + nn) * H3;
            ks[nn][d] = r[Cdim + d] * scale;   // k
            vs[nn][d] = r[2 * Cdim + d];       // v
        }
        __syncthreads();
        for (int nn = 0; nn < cnt; nn++) {
            float rk[3], rv[3];
#pragma unroll
            for (int i = 0; i < 3; i++) { rk[i] = ks[nn][ty * 3 + i]; rv[i] = vs[nn][tx * 3 + i]; }
#pragma unroll
            for (int i = 0; i < 3; i++)
#pragma unroll
                for (int j = 0; j < 3; j++)
                    acc[i][j] = fmaf(rk[i], rv[j], acc[i][j]);
        }
        __syncthreads();
    }

#pragma unroll
    for (int i = 0; i < 3; i++)
#pragma unroll
        for (int j = 0; j < 3; j++)
            at[ty * 3 + i][tx * 3 + j] = acc[i][j];
    __syncthreads();

    if (tid < HD) {
        float m = -1e30f;
        for (int e = 0; e < HD; e++) m = fmaxf(m, at[tid][e]);
        float s = 0.f;
        for (int e = 0; e < HD; e++) { float t = expf(at[tid][e] - m); at[tid][e] = t; s += t; }
        float inv = 1.f / s;
        float* o = attn_out + (size_t)bh * (HD * HD) + tid * HD;
        for (int e = 0; e < HD; e++) o[e] = at[tid][e] * inv;
    }
}

// ---------------------------------------------------------------------------
// Channel attention, stage B: out[b,n,h*48+d] = sum_e attn[d,e] * q[b,n,h,e]
// Block = (b,h) x 8 token rows; 384 threads = 8 rows x 48 d.
// ---------------------------------------------------------------------------
__global__ __launch_bounds__(384)
void attnB_kernel(const float* __restrict__ qkv, const float* __restrict__ attn,
                  float* __restrict__ out)
{
    __shared__ float at[48 * 49];
    __shared__ float qs[8][48];

    int bh = blockIdx.x;
    int b = bh >> 3, h = bh & 7;
    int n0 = blockIdx.y * 8;
    int tid = threadIdx.x;

    const float* ab = attn + (size_t)bh * (HD * HD);
    for (int idx = tid; idx < HD * HD; idx += 384) {
        int d = idx / HD, e = idx % HD;
        at[d * 49 + e] = ab[idx];
    }
    int nl = tid / HD;
    int d  = tid % HD;
    qs[nl][d] = qkv[((size_t)b * Ntok + n0 + nl) * H3 + h * HD + d];  // q
    __syncthreads();

    float acc = 0.f;
#pragma unroll
    for (int e = 0; e < HD; e++)
        acc = fmaf(at[d * 49 + e], qs[nl][e], acc);

    out[((size_t)b * Ntok + n0 + nl) * Cdim + h * HD + d] = acc;
}

// ---------------------------------------------------------------------------
// Launch
// ---------------------------------------------------------------------------
extern "C" void kernel_launch(void* const* d_in, const int* in_sizes, int n_in,
                              void* d_out, int out_size)
{
    const float* x       = (const float*)d_in[0];
    // d_in[1]=H, d_in[2]=W (28, hardcoded)
    const float* cpe0_w  = (const float*)d_in[3];
    const float* cpe0_b  = (const float*)d_in[4];
    const float* cpe1_w  = (const float*)d_in[5];
    const float* cpe1_b  = (const float*)d_in[6];
    const float* norm1_g = (const float*)d_in[7];
    const float* norm1_b = (const float*)d_in[8];
    const float* qkv_w   = (const float*)d_in[9];
    const float* proj_w  = (const float*)d_in[10];
    const float* proj_b  = (const float*)d_in[11];
    const float* norm2_g = (const float*)d_in[12];
    const float* norm2_b = (const float*)d_in[13];
    const float* fc1_w   = (const float*)d_in[14];
    const float* fc1_b   = (const float*)d_in[15];
    const float* fc2_w   = (const float*)d_in[16];
    const float* fc2_b   = (const float*)d_in[17];
    float* out = (float*)d_out;

    float *xa, *ln, *qkvb, *attn, *att, *xb, *hbuf;
    cudaGetSymbolAddress((void**)&xa,   g_xa);
    cudaGetSymbolAddress((void**)&ln,   g_ln);
    cudaGetSymbolAddress((void**)&qkvb, g_qkv);
    cudaGetSymbolAddress((void**)&attn, g_attn);
    cudaGetSymbolAddress((void**)&att,  g_att);
    cudaGetSymbolAddress((void**)&xb,   g_xb);
    cudaGetSymbolAddress((void**)&hbuf, g_h);

    dim3 cpeGrid(Ntok, Bsz);

    // xa = cpe0(x)
    cpe_kernel<<<cpeGrid, Cdim>>>(x, cpe0_w, cpe0_b, xa);
    // ln1
    ln_kernel<<<NT / 8, 256>>>(xa, norm1_g, norm1_b, ln);
    // qkv = ln1 @ qkv_w^T
    gemm_nt<0><<<dim3(H3 / GBN, NT / GBM), 256>>>(ln, qkv_w, nullptr, nullptr, qkvb, NT, H3, Cdim);
    // channel attention
    attnA_kernel<<<Bsz * NH, 256>>>(qkvb, attn);
    attnB_kernel<<<dim3(Bsz * NH, Ntok / 8), 384>>>(qkvb, attn, att);
    // xb = xa + att @ proj_w^T + proj_b
    gemm_nt<3><<<dim3(Cdim / GBN, NT / GBM), 256>>>(att, proj_w, proj_b, xa, xb, NT, Cdim, Cdim);
    // xc = cpe1(xb) -> stored into xa
    cpe_kernel<<<cpeGrid, Cdim>>>(xb, cpe1_w, cpe1_b, xa);
    // ln2
    ln_kernel<<<NT / 8, 256>>>(xa, norm2_g, norm2_b, ln);
    // h = gelu(ln2 @ fc1^T + b1)
    gemm_nt<2><<<dim3(HID / GBN, NT / GBM), 256>>>(ln, fc1_w, fc1_b, nullptr, hbuf, NT, HID, Cdim);
    // out = xc + h @ fc2^T + b2
    gemm_nt<3><<<dim3(Cdim / GBN, NT / GBM), 256>>>(hbuf, fc2_w, fc2_b, xa, out, NT, Cdim, HID);
}

// round 2
// speedup vs baseline: 2.3480x; 2.3480x over previous
#include <cuda_runtime.h>
#include <cuda_bf16.h>
#include <math.h>

// ---------------------------------------------------------------------------
// ChannelBlock: B=32, N=784 (28x28), C=384, heads=8, hd=48, MLP hidden=1536
// TF32 tensor-core GEMMs (mma.sync m16n8k8), fused cpe+LN, split-N attnA.
// ---------------------------------------------------------------------------

#define Bsz   32
#define Ntok  784
#define Cdim  384
#define NT    (Bsz * Ntok)     // 25088
#define H3    (3 * Cdim)       // 1152
#define HID   1536
#define NH    8
#define HD    48

// scratch (static device memory; no allocation anywhere)
__device__ float g_xa  [(size_t)NT * Cdim];
__device__ float g_ln  [(size_t)NT * Cdim];
__device__ float g_qkv [(size_t)NT * H3];
__device__ float g_attn[(size_t)Bsz * NH * HD * HD];   // raw logits (atomic acc)
__device__ float g_attn2[(size_t)Bsz * NH * HD * HD];  // softmaxed
__device__ float g_att [(size_t)NT * Cdim];
__device__ float g_xb  [(size_t)NT * Cdim];
__device__ float g_h   [(size_t)NT * HID];

__device__ __forceinline__ unsigned f2tf(float x) {
    unsigned u;
    asm("cvt.rna.tf32.f32 %0, %1;" : "=r"(u) : "f"(x));
    return u;
}

// ---------------------------------------------------------------------------
// Fused depthwise 3x3 conv (SAME) + residual + LayerNorm.
// Block = one token (384 threads = channels). Writes y (conv+res) and yln (LN).
// ---------------------------------------------------------------------------
__global__ __launch_bounds__(Cdim)
void cpe_ln_kernel(const float* __restrict__ x,
                   const float* __restrict__ w,
                   const float* __restrict__ bias,
                   const float* __restrict__ lng,
                   const float* __restrict__ lnb,
                   float* __restrict__ y,
                   float* __restrict__ yln)
{
    int c = threadIdx.x;               // 0..383
    int n = blockIdx.x;                // 0..783
    int b = blockIdx.y;                // 0..31
    int i = n / 28, j = n % 28;

    const float* xb = x + (size_t)b * Ntok * Cdim + c;
    float acc = bias[c];
    const float* wc = w + c * 9;
#pragma unroll
    for (int di = -1; di <= 1; di++) {
        int ii = i + di;
        if (ii < 0 || ii >= 28) continue;
#pragma unroll
        for (int dj = -1; dj <= 1; dj++) {
            int jj = j + dj;
            if (jj < 0 || jj >= 28) continue;
            acc += wc[(di + 1) * 3 + (dj + 1)] * xb[(size_t)(ii * 28 + jj) * Cdim];
        }
    }
    size_t idx = ((size_t)b * Ntok + n) * Cdim + c;
    float val = x[idx] + acc;
    y[idx] = val;

    // block reduce mean / meansq over 384 threads (12 warps)
    __shared__ float red[24];
    __shared__ float stats[2];
    float s = val, sq = val * val;
#pragma unroll
    for (int o = 16; o; o >>= 1) {
        s  += __shfl_xor_sync(0xffffffffu, s,  o);
        sq += __shfl_xor_sync(0xffffffffu, sq, o);
    }
    int warp = c >> 5, lane = c & 31;
    if (lane == 0) { red[warp] = s; red[12 + warp] = sq; }
    __syncthreads();
    if (c == 0) {
        float ts = 0.f, tq = 0.f;
#pragma unroll
        for (int k = 0; k < 12; k++) { ts += red[k]; tq += red[12 + k]; }
        float mean = ts * (1.f / Cdim);
        float var  = tq * (1.f / Cdim) - mean * mean;
        stats[0] = mean;
        stats[1] = rsqrtf(var + 1e-5f);
    }
    __syncthreads();
    float mean = stats[0], rs = stats[1];
    yln[idx] = (val - mean) * rs * lng[c] + lnb[c];
}

// ---------------------------------------------------------------------------
// TF32 tensor-core GEMM, NT form: C[m,n] = sum_k A[m,k] * W[n,k] (+ epilogue)
// BM=BN=128, BK=32, 256 threads (8 warps, 2m x 4n, warp tile 64x32).
// EPI: 0 = none, 2 = +bias + exact GELU, 3 = +bias + residual
// Requires M%128==0, N%128==0, K%32==0, 16B-aligned rows (all true here).
// ---------------------------------------------------------------------------
#define BM 128
#define BN 128
#define BK 32
#define SKP (BK + 4)   // 36-word row stride: conflict-free LDS pattern

template<int EPI>
__global__ __launch_bounds__(256, 2)
void gemm_tf32(const float* __restrict__ A, const float* __restrict__ W,
               const float* __restrict__ bias, const float* __restrict__ res,
               float* __restrict__ C, int M, int N, int K)
{
    __shared__ unsigned As[BM][SKP];
    __shared__ unsigned Bs[BN][SKP];

    int tid = threadIdx.x;
    int row0 = blockIdx.y * BM;
    int col0 = blockIdx.x * BN;
    int warp = tid >> 5, lane = tid & 31;
    int wm = (warp & 1) * 64;
    int wn = (warp >> 1) * 32;
    int g = lane >> 2, tig = lane & 3;

    float acc[4][4][4];
#pragma unroll
    for (int mi = 0; mi < 4; mi++)
#pragma unroll
        for (int ni = 0; ni < 4; ni++)
#pragma unroll
            for (int r = 0; r < 4; r++) acc[mi][ni][r] = 0.f;

    for (int kt = 0; kt < K; kt += BK) {
#pragma unroll
        for (int i = 0; i < 4; i++) {
            int fid = tid + i * 256;       // 0..1023
            int m  = fid >> 3;             // 0..127
            int k4 = fid & 7;              // 0..7 (float4 index)
            float4 va = *(const float4*)(A + (size_t)(row0 + m) * K + kt + k4 * 4);
            As[m][k4 * 4 + 0] = f2tf(va.x);
            As[m][k4 * 4 + 1] = f2tf(va.y);
            As[m][k4 * 4 + 2] = f2tf(va.z);
            As[m][k4 * 4 + 3] = f2tf(va.w);
            float4 vb = *(const float4*)(W + (size_t)(col0 + m) * K + kt + k4 * 4);
            Bs[m][k4 * 4 + 0] = f2tf(vb.x);
            Bs[m][k4 * 4 + 1] = f2tf(vb.y);
            Bs[m][k4 * 4 + 2] = f2tf(vb.z);
            Bs[m][k4 * 4 + 3] = f2tf(vb.w);
        }
        __syncthreads();

#pragma unroll
        for (int kk = 0; kk < BK; kk += 8) {
            unsigned af[4][4], bf[4][2];
#pragma unroll
            for (int mi = 0; mi < 4; mi++) {
                int r = wm + mi * 16;
                af[mi][0] = As[r + g][kk + tig];
                af[mi][1] = As[r + g + 8][kk + tig];
                af[mi][2] = As[r + g][kk + tig + 4];
                af[mi][3] = As[r + g + 8][kk + tig + 4];
            }
#pragma unroll
            for (int ni = 0; ni < 4; ni++) {
                int cc = wn + ni * 8;
                bf[ni][0] = Bs[cc + g][kk + tig];
                bf[ni][1] = Bs[cc + g][kk + tig + 4];
            }
#pragma unroll
            for (int mi = 0; mi < 4; mi++)
#pragma unroll
                for (int ni = 0; ni < 4; ni++) {
                    asm volatile(
                        "mma.sync.aligned.m16n8k8.row.col.f32.tf32.tf32.f32 "
                        "{%0,%1,%2,%3}, {%4,%5,%6,%7}, {%8,%9}, {%0,%1,%2,%3};"
                        : "+f"(acc[mi][ni][0]), "+f"(acc[mi][ni][1]),
                          "+f"(acc[mi][ni][2]), "+f"(acc[mi][ni][3])
                        : "r"(af[mi][0]), "r"(af[mi][1]), "r"(af[mi][2]), "r"(af[mi][3]),
                          "r"(bf[ni][0]), "r"(bf[ni][1]));
                }
        }
        __syncthreads();
    }

    // epilogue. C fragment (m16n8): c0=C[g][2t], c1=C[g][2t+1], c2=C[g+8][2t], c3=C[g+8][2t+1]
#pragma unroll
    for (int mi = 0; mi < 4; mi++) {
#pragma unroll
        for (int ni = 0; ni < 4; ni++) {
#pragma unroll
            for (int r = 0; r < 4; r++) {
                int row = row0 + wm + mi * 16 + g + (r >> 1) * 8;
                int col = col0 + wn + ni * 8 + 2 * tig + (r & 1);
                size_t idx = (size_t)row * N + col;
                float v = acc[mi][ni][r];
                if (EPI == 2) {
                    v += bias[col];
                    v = 0.5f * v * (1.f + erff(v * 0.7071067811865475f));
                } else if (EPI == 3) {
                    v += bias[col] + res[idx];
                }
                C[idx] = v;
            }
        }
    }
}

// ---------------------------------------------------------------------------
// Channel attention stage A (partial): accumulate (k*s)^T v into raw logits.
// Grid (256 bh, 7 chunks of 112 tokens). Each thread owns a 3x3 tile of 48x48.
// ---------------------------------------------------------------------------
__global__ __launch_bounds__(256)
void attnA_partial(const float* __restrict__ qkv, float* __restrict__ raw)
{
    __shared__ float ks[32][49];
    __shared__ float vs[32][49];

    int bh = blockIdx.x;
    int b = bh >> 3, h = bh & 7;
    int nstart = blockIdx.y * 112;
    int nend   = nstart + 112;
    int tid = threadIdx.x;
    int tx = tid & 15, ty = tid >> 4;
    const float scale = 0.14433756729740643f;   // 48^-0.5

    float acc[3][3] = {{0.f,0.f,0.f},{0.f,0.f,0.f},{0.f,0.f,0.f}};
    const float* base = qkv + (size_t)b * Ntok * H3 + h * HD;

    for (int n0 = nstart; n0 < nend; n0 += 32) {
        int cnt = min(32, nend - n0);
        for (int idx = tid; idx < cnt * HD; idx += 256) {
            int nn = idx / HD, d = idx % HD;
            const float* r = base + (size_t)(n0 + nn) * H3;
            ks[nn][d] = r[Cdim + d] * scale;   // k
            vs[nn][d] = r[2 * Cdim + d];       // v
        }
        __syncthreads();
        for (int nn = 0; nn < cnt; nn++) {
            float rk[3], rv[3];
#pragma unroll
            for (int i = 0; i < 3; i++) { rk[i] = ks[nn][ty * 3 + i]; rv[i] = vs[nn][tx * 3 + i]; }
#pragma unroll
            for (int i = 0; i < 3; i++)
#pragma unroll
                for (int j = 0; j < 3; j++)
                    acc[i][j] = fmaf(rk[i], rv[j], acc[i][j]);
        }
        __syncthreads();
    }

    float* o = raw + (size_t)bh * (HD * HD);
#pragma unroll
    for (int i = 0; i < 3; i++)
#pragma unroll
        for (int j = 0; j < 3; j++)
            atomicAdd(&o[(ty * 3 + i) * HD + tx * 3 + j], acc[i][j]);
}

// softmax over last dim of 48x48 logits; one block per (b,h), 64 threads.
__global__ __launch_bounds__(64)
void attnA_softmax(const float* __restrict__ raw, float* __restrict__ attn_out)
{
    int bh = blockIdx.x;
    int d = threadIdx.x;
    if (d >= HD) return;
    const float* r = raw + (size_t)bh * (HD * HD) + d * HD;
    float* o = attn_out + (size_t)bh * (HD * HD) + d * HD;
    float m = -1e30f;
#pragma unroll
    for (int e = 0; e < HD; e++) m = fmaxf(m, r[e]);
    float s = 0.f;
    float t[HD];
#pragma unroll
    for (int e = 0; e < HD; e++) { t[e] = expf(r[e] - m); s += t[e]; }
    float inv = 1.f / s;
#pragma unroll
    for (int e = 0; e < HD; e++) o[e] = t[e] * inv;
}

// ---------------------------------------------------------------------------
// Channel attention stage B: out[b,n,h*48+d] = sum_e attn[d,e] * q[b,n,h,e]
// ---------------------------------------------------------------------------
__global__ __launch_bounds__(384)
void attnB_kernel(const float* __restrict__ qkv, const float* __restrict__ attn,
                  float* __restrict__ out)
{
    __shared__ float at[48 * 49];
    __shared__ float qs[8][48];

    int bh = blockIdx.x;
    int b = bh >> 3, h = bh & 7;
    int n0 = blockIdx.y * 8;
    int tid = threadIdx.x;

    const float* ab = attn + (size_t)bh * (HD * HD);
    for (int idx = tid; idx < HD * HD; idx += 384) {
        int d = idx / HD, e = idx % HD;
        at[d * 49 + e] = ab[idx];
    }
    int nl = tid / HD;
    int d  = tid % HD;
    qs[nl][d] = qkv[((size_t)b * Ntok + n0 + nl) * H3 + h * HD + d];  // q
    __syncthreads();

    float acc = 0.f;
#pragma unroll
    for (int e = 0; e < HD; e++)
        acc = fmaf(at[d * 49 + e], qs[nl][e], acc);

    out[((size_t)b * Ntok + n0 + nl) * Cdim + h * HD + d] = acc;
}

// ---------------------------------------------------------------------------
// Launch
// ---------------------------------------------------------------------------
extern "C" void kernel_launch(void* const* d_in, const int* in_sizes, int n_in,
                              void* d_out, int out_size)
{
    const float* x       = (const float*)d_in[0];
    const float* cpe0_w  = (const float*)d_in[3];
    const float* cpe0_b  = (const float*)d_in[4];
    const float* cpe1_w  = (const float*)d_in[5];
    const float* cpe1_b  = (const float*)d_in[6];
    const float* norm1_g = (const float*)d_in[7];
    const float* norm1_b = (const float*)d_in[8];
    const float* qkv_w   = (const float*)d_in[9];
    const float* proj_w  = (const float*)d_in[10];
    const float* proj_b  = (const float*)d_in[11];
    const float* norm2_g = (const float*)d_in[12];
    const float* norm2_b = (const float*)d_in[13];
    const float* fc1_w   = (const float*)d_in[14];
    const float* fc1_b   = (const float*)d_in[15];
    const float* fc2_w   = (const float*)d_in[16];
    const float* fc2_b   = (const float*)d_in[17];
    float* out = (float*)d_out;

    float *xa, *ln, *qkvb, *attn, *attn2, *att, *xb, *hbuf;
    cudaGetSymbolAddress((void**)&xa,    g_xa);
    cudaGetSymbolAddress((void**)&ln,    g_ln);
    cudaGetSymbolAddress((void**)&qkvb,  g_qkv);
    cudaGetSymbolAddress((void**)&attn,  g_attn);
    cudaGetSymbolAddress((void**)&attn2, g_attn2);
    cudaGetSymbolAddress((void**)&att,   g_att);
    cudaGetSymbolAddress((void**)&xb,    g_xb);
    cudaGetSymbolAddress((void**)&hbuf,  g_h);

    dim3 cpeGrid(Ntok, Bsz);

    // zero raw attention logits (graph-capturable memset node)
    cudaMemsetAsync(attn, 0, (size_t)Bsz * NH * HD * HD * sizeof(float));

    // xa = cpe0(x); ln = LN1(xa)
    cpe_ln_kernel<<<cpeGrid, Cdim>>>(x, cpe0_w, cpe0_b, norm1_g, norm1_b, xa, ln);
    // qkv = ln1 @ qkv_w^T
    gemm_tf32<0><<<dim3(H3 / BN, NT / BM), 256>>>(ln, qkv_w, nullptr, nullptr, qkvb, NT, H3, Cdim);
    // channel attention
    attnA_partial<<<dim3(Bsz * NH, 7), 256>>>(qkvb, attn);
    attnA_softmax<<<Bsz * NH, 64>>>(attn, attn2);
    attnB_kernel<<<dim3(Bsz * NH, Ntok / 8), 384>>>(qkvb, attn2, att);
    // xb = xa + att @ proj_w^T + proj_b
    gemm_tf32<3><<<dim3(Cdim / BN, NT / BM), 256>>>(att, proj_w, proj_b, xa, xb, NT, Cdim, Cdim);
    // xc = cpe1(xb) -> xa ; ln = LN2(xc)
    cpe_ln_kernel<<<cpeGrid, Cdim>>>(xb, cpe1_w, cpe1_b, norm2_g, norm2_b, xa, ln);
    // h = gelu(ln2 @ fc1^T + b1)
    gemm_tf32<2><<<dim3(HID / BN, NT / BM), 256>>>(ln, fc1_w, fc1_b, nullptr, hbuf, NT, HID, Cdim);
    // out = xc + h @ fc2^T + b2
    gemm_tf32<3><<<dim3(Cdim / BN, NT / BM), 256>>>(hbuf, fc2_w, fc2_b, xa, out, NT, Cdim, HID);
}

// round 3
// speedup vs baseline: 2.6011x; 1.1078x over previous
#include <cuda_runtime.h>
#include <cuda_bf16.h>
#include <math.h>

// ---------------------------------------------------------------------------
// ChannelBlock: B=32, N=784 (28x28), C=384, heads=8, hd=48, MLP hidden=1536
// bf16 tensor-core GEMMs (mma.sync m16n8k16) + cp.async double buffering.
// Activations staged in bf16 where they feed a GEMM; accumulation fp32.
// ---------------------------------------------------------------------------

#define Bsz   32
#define Ntok  784
#define Cdim  384
#define NT    (Bsz * Ntok)     // 25088
#define H3    (3 * Cdim)       // 1152
#define HID   1536
#define NH    8
#define HD    48

typedef __nv_bfloat16 bf16;

// scratch (static device memory; no allocation anywhere)
__device__ float g_xa  [(size_t)NT * Cdim];
__device__ bf16  g_ln  [(size_t)NT * Cdim];
__device__ float g_qkv [(size_t)NT * H3];
__device__ float g_attn[(size_t)Bsz * NH * HD * HD];   // raw logits (atomic acc)
__device__ float g_attn2[(size_t)Bsz * NH * HD * HD];  // softmaxed
__device__ bf16  g_att [(size_t)NT * Cdim];
__device__ float g_xb  [(size_t)NT * Cdim];
__device__ bf16  g_h   [(size_t)NT * HID];
// bf16 weights: qkv | proj | fc1 | fc2
#define W_QKV 0
#define W_PROJ (H3 * Cdim)                       // 442368
#define W_FC1  (W_PROJ + Cdim * Cdim)            // +147456
#define W_FC2  (W_FC1 + HID * Cdim)              // +589824
#define W_TOT  (W_FC2 + Cdim * HID)              // +589824
__device__ bf16  g_wbf [(size_t)W_TOT];

// ---------------------------------------------------------------------------
__global__ void cvt_w_kernel(const float* __restrict__ in, bf16* __restrict__ out, int n)
{
    int i = blockIdx.x * blockDim.x + threadIdx.x;
    if (i < n) out[i] = __float2bfloat16(in[i]);
}

// ---------------------------------------------------------------------------
// Fused depthwise 3x3 conv (SAME) + residual + LayerNorm (bf16 LN output).
// ---------------------------------------------------------------------------
__global__ __launch_bounds__(Cdim)
void cpe_ln_kernel(const float* __restrict__ x,
                   const float* __restrict__ w,
                   const float* __restrict__ bias,
                   const float* __restrict__ lng,
                   const float* __restrict__ lnb,
                   float* __restrict__ y,
                   bf16* __restrict__ yln)
{
    int c = threadIdx.x;               // 0..383
    int n = blockIdx.x;                // 0..783
    int b = blockIdx.y;                // 0..31
    int i = n / 28, j = n % 28;

    const float* xb = x + (size_t)b * Ntok * Cdim + c;
    float acc = bias[c];
    const float* wc = w + c * 9;
#pragma unroll
    for (int di = -1; di <= 1; di++) {
        int ii = i + di;
        if (ii < 0 || ii >= 28) continue;
#pragma unroll
        for (int dj = -1; dj <= 1; dj++) {
            int jj = j + dj;
            if (jj < 0 || jj >= 28) continue;
            acc += wc[(di + 1) * 3 + (dj + 1)] * xb[(size_t)(ii * 28 + jj) * Cdim];
        }
    }
    size_t idx = ((size_t)b * Ntok + n) * Cdim + c;
    float val = x[idx] + acc;
    y[idx] = val;

    __shared__ float red[24];
    __shared__ float stats[2];
    float s = val, sq = val * val;
#pragma unroll
    for (int o = 16; o; o >>= 1) {
        s  += __shfl_xor_sync(0xffffffffu, s,  o);
        sq += __shfl_xor_sync(0xffffffffu, sq, o);
    }
    int warp = c >> 5, lane = c & 31;
    if (lane == 0) { red[warp] = s; red[12 + warp] = sq; }
    __syncthreads();
    if (c == 0) {
        float ts = 0.f, tq = 0.f;
#pragma unroll
        for (int k = 0; k < 12; k++) { ts += red[k]; tq += red[12 + k]; }
        float mean = ts * (1.f / Cdim);
        float var  = tq * (1.f / Cdim) - mean * mean;
        stats[0] = mean;
        stats[1] = rsqrtf(var + 1e-5f);
    }
    __syncthreads();
    float mean = stats[0], rs = stats[1];
    yln[idx] = __float2bfloat16((val - mean) * rs * lng[c] + lnb[c]);
}

// ---------------------------------------------------------------------------
// bf16 tensor-core GEMM, NT form: C[m,n] = sum_k A[m,k] * W[n,k] (+ epilogue)
// BM=BN=128, BK=32, 256 threads (8 warps, 2m x 4n, warp tile 64x32).
// cp.async double-buffered. A, W are bf16; accumulate fp32.
// EPI: 0 = none -> fp32 ; 2 = +bias + exact GELU -> bf16 ; 3 = +bias+res -> fp32
// ---------------------------------------------------------------------------
#define BM 128
#define BN 128
#define BK 32
#define WSTR 20   // 32-bit words per smem row (80B): conflict-free LDS & STS

__device__ __forceinline__ void cp16(unsigned saddr, const void* g)
{
    asm volatile("cp.async.cg.shared.global [%0], [%1], 16;\n" :: "r"(saddr), "l"(g));
}

template<int EPI>
__global__ __launch_bounds__(256, 2)
void gemm_bf16(const bf16* __restrict__ A, const bf16* __restrict__ W,
               const float* __restrict__ bias, const float* __restrict__ res,
               void* __restrict__ Cout, int M, int N, int K)
{
    __shared__ alignas(16) unsigned As[2][BM * WSTR];
    __shared__ alignas(16) unsigned Bs[2][BN * WSTR];

    int tid = threadIdx.x;
    int row0 = blockIdx.y * BM;
    int col0 = blockIdx.x * BN;
    int warp = tid >> 5, lane = tid & 31;
    int wm = (warp & 1) * 64;
    int wn = (warp >> 1) * 32;
    int g = lane >> 2, t = lane & 3;

    // loader mapping: each thread copies two 16B chunks per tile per matrix
    int lc = tid >> 6;        // 0..3  (16B chunk within row)
    int lm = tid & 63;        // row base; rows lm and lm+64

    unsigned asBase = (unsigned)__cvta_generic_to_shared(&As[0][0]);
    unsigned bsBase = (unsigned)__cvta_generic_to_shared(&Bs[0][0]);
    const unsigned stageBytesA = BM * WSTR * 4;
    const unsigned stageBytesB = BN * WSTR * 4;

    float acc[4][4][4];
#pragma unroll
    for (int mi = 0; mi < 4; mi++)
#pragma unroll
        for (int ni = 0; ni < 4; ni++)
#pragma unroll
            for (int r = 0; r < 4; r++) acc[mi][ni][r] = 0.f;

    int NS = K / BK;

    // preload stage 0
    {
        const bf16* Ab = A + (size_t)row0 * K + lc * 8;
        const bf16* Wb = W + (size_t)col0 * K + lc * 8;
#pragma unroll
        for (int i = 0; i < 2; i++) {
            int m = lm + i * 64;
            cp16(asBase + (m * WSTR + lc * 4) * 4, Ab + (size_t)m * K);
            cp16(bsBase + (m * WSTR + lc * 4) * 4, Wb + (size_t)m * K);
        }
        asm volatile("cp.async.commit_group;\n");
    }

    for (int s = 0; s < NS; s++) {
        if (s + 1 < NS) {
            int kt = (s + 1) * BK;
            unsigned aoff = ((s + 1) & 1) ? stageBytesA : 0;
            unsigned boff = ((s + 1) & 1) ? stageBytesB : 0;
            const bf16* Ab = A + (size_t)row0 * K + kt + lc * 8;
            const bf16* Wb = W + (size_t)col0 * K + kt + lc * 8;
#pragma unroll
            for (int i = 0; i < 2; i++) {
                int m = lm + i * 64;
                cp16(asBase + aoff + (m * WSTR + lc * 4) * 4, Ab + (size_t)m * K);
                cp16(bsBase + boff + (m * WSTR + lc * 4) * 4, Wb + (size_t)m * K);
            }
            asm volatile("cp.async.commit_group;\n");
            asm volatile("cp.async.wait_group 1;\n");
        } else {
            asm volatile("cp.async.wait_group 0;\n");
        }
        __syncthreads();

        const unsigned* as = As[s & 1];
        const unsigned* bs = Bs[s & 1];
#pragma unroll
        for (int kk = 0; kk < BK; kk += 16) {
            int wb = kk / 2;   // word base within row
            unsigned af[4][4], bf[4][2];
#pragma unroll
            for (int mi = 0; mi < 4; mi++) {
                int r = wm + mi * 16;
                af[mi][0] = as[(r + g) * WSTR + wb + t];
                af[mi][1] = as[(r + g + 8) * WSTR + wb + t];
                af[mi][2] = as[(r + g) * WSTR + wb + t + 4];
                af[mi][3] = as[(r + g + 8) * WSTR + wb + t + 4];
            }
#pragma unroll
            for (int ni = 0; ni < 4; ni++) {
                int cc = wn + ni * 8 + g;
                bf[ni][0] = bs[cc * WSTR + wb + t];
                bf[ni][1] = bs[cc * WSTR + wb + t + 4];
            }
#pragma unroll
            for (int mi = 0; mi < 4; mi++)
#pragma unroll
                for (int ni = 0; ni < 4; ni++) {
                    asm volatile(
                        "mma.sync.aligned.m16n8k16.row.col.f32.bf16.bf16.f32 "
                        "{%0,%1,%2,%3}, {%4,%5,%6,%7}, {%8,%9}, {%0,%1,%2,%3};"
                        : "+f"(acc[mi][ni][0]), "+f"(acc[mi][ni][1]),
                          "+f"(acc[mi][ni][2]), "+f"(acc[mi][ni][3])
                        : "r"(af[mi][0]), "r"(af[mi][1]), "r"(af[mi][2]), "r"(af[mi][3]),
                          "r"(bf[ni][0]), "r"(bf[ni][1]));
                }
        }
        __syncthreads();
    }

    // epilogue: c0=C[g][2t], c1=C[g][2t+1], c2=C[g+8][2t], c3=C[g+8][2t+1]
#pragma unroll
    for (int mi = 0; mi < 4; mi++) {
#pragma unroll
        for (int ni = 0; ni < 4; ni++) {
#pragma unroll
            for (int r = 0; r < 4; r++) {
                int row = row0 + wm + mi * 16 + g + (r >> 1) * 8;
                int col = col0 + wn + ni * 8 + 2 * t + (r & 1);
                size_t idx = (size_t)row * N + col;
                float v = acc[mi][ni][r];
                if (EPI == 0) {
                    ((float*)Cout)[idx] = v;
                } else if (EPI == 2) {
                    v += bias[col];
                    v = 0.5f * v * (1.f + erff(v * 0.7071067811865475f));
                    ((bf16*)Cout)[idx] = __float2bfloat16(v);
                } else if (EPI == 3) {
                    v += bias[col] + res[idx];
                    ((float*)Cout)[idx] = v;
                }
            }
        }
    }
}

// ---------------------------------------------------------------------------
// Channel attention stage A (partial): accumulate (k*s)^T v into raw logits.
// ---------------------------------------------------------------------------
__global__ __launch_bounds__(256)
void attnA_partial(const float* __restrict__ qkv, float* __restrict__ raw)
{
    __shared__ float ks[32][49];
    __shared__ float vs[32][49];

    int bh = blockIdx.x;
    int b = bh >> 3, h = bh & 7;
    int nstart = blockIdx.y * 112;
    int nend   = nstart + 112;
    int tid = threadIdx.x;
    int tx = tid & 15, ty = tid >> 4;
    const float scale = 0.14433756729740643f;   // 48^-0.5

    float acc[3][3] = {{0.f,0.f,0.f},{0.f,0.f,0.f},{0.f,0.f,0.f}};
    const float* base = qkv + (size_t)b * Ntok * H3 + h * HD;

    for (int n0 = nstart; n0 < nend; n0 += 32) {
        int cnt = min(32, nend - n0);
        for (int idx = tid; idx < cnt * HD; idx += 256) {
            int nn = idx / HD, d = idx % HD;
            const float* r = base + (size_t)(n0 + nn) * H3;
            ks[nn][d] = r[Cdim + d] * scale;   // k
            vs[nn][d] = r[2 * Cdim + d];       // v
        }
        __syncthreads();
        for (int nn = 0; nn < cnt; nn++) {
            float rk[3], rv[3];
#pragma unroll
            for (int i = 0; i < 3; i++) { rk[i] = ks[nn][ty * 3 + i]; rv[i] = vs[nn][tx * 3 + i]; }
#pragma unroll
            for (int i = 0; i < 3; i++)
#pragma unroll
                for (int j = 0; j < 3; j++)
                    acc[i][j] = fmaf(rk[i], rv[j], acc[i][j]);
        }
        __syncthreads();
    }

    float* o = raw + (size_t)bh * (HD * HD);
#pragma unroll
    for (int i = 0; i < 3; i++)
#pragma unroll
        for (int j = 0; j < 3; j++)
            atomicAdd(&o[(ty * 3 + i) * HD + tx * 3 + j], acc[i][j]);
}

// softmax over last dim of 48x48 logits; one thread per (bh, d) row.
__global__ __launch_bounds__(256)
void attnA_softmax(const float* __restrict__ raw, float* __restrict__ attn_out)
{
    int idx = blockIdx.x * 256 + threadIdx.x;
    if (idx >= Bsz * NH * HD) return;
    const float* r = raw + (size_t)idx * HD;
    float* o = attn_out + (size_t)idx * HD;
    float m = -1e30f;
#pragma unroll
    for (int e = 0; e < HD; e++) m = fmaxf(m, r[e]);
    float s = 0.f;
    float tv[HD];
#pragma unroll
    for (int e = 0; e < HD; e++) { tv[e] = expf(r[e] - m); s += tv[e]; }
    float inv = 1.f / s;
#pragma unroll
    for (int e = 0; e < HD; e++) o[e] = tv[e] * inv;
}

// ---------------------------------------------------------------------------
// Channel attention stage B: out[b,n,h*48+d] = sum_e attn[d,e] * q[b,n,h,e]
// Writes bf16 (feeds proj GEMM).
// ---------------------------------------------------------------------------
__global__ __launch_bounds__(384)
void attnB_kernel(const float* __restrict__ qkv, const float* __restrict__ attn,
                  bf16* __restrict__ out)
{
    __shared__ float at[48 * 49];
    __shared__ float qs[8][48];

    int bh = blockIdx.x;
    int b = bh >> 3, h = bh & 7;
    int n0 = blockIdx.y * 8;
    int tid = threadIdx.x;

    const float* ab = attn + (size_t)bh * (HD * HD);
    for (int idx = tid; idx < HD * HD; idx += 384) {
        int d = idx / HD, e = idx % HD;
        at[d * 49 + e] = ab[idx];
    }
    int nl = tid / HD;
    int d  = tid % HD;
    qs[nl][d] = qkv[((size_t)b * Ntok + n0 + nl) * H3 + h * HD + d];  // q
    __syncthreads();

    float acc = 0.f;
#pragma unroll
    for (int e = 0; e < HD; e++)
        acc = fmaf(at[d * 49 + e], qs[nl][e], acc);

    out[((size_t)b * Ntok + n0 + nl) * Cdim + h * HD + d] = __float2bfloat16(acc);
}

// ---------------------------------------------------------------------------
// Launch
// ---------------------------------------------------------------------------
extern "C" void kernel_launch(void* const* d_in, const int* in_sizes, int n_in,
                              void* d_out, int out_size)
{
    const float* x       = (const float*)d_in[0];
    const float* cpe0_w  = (const float*)d_in[3];
    const float* cpe0_b  = (const float*)d_in[4];
    const float* cpe1_w  = (const float*)d_in[5];
    const float* cpe1_b  = (const float*)d_in[6];
    const float* norm1_g = (const float*)d_in[7];
    const float* norm1_b = (const float*)d_in[8];
    const float* qkv_w   = (const float*)d_in[9];
    const float* proj_w  = (const float*)d_in[10];
    const float* proj_b  = (const float*)d_in[11];
    const float* norm2_g = (const float*)d_in[12];
    const float* norm2_b = (const float*)d_in[13];
    const float* fc1_w   = (const float*)d_in[14];
    const float* fc1_b   = (const float*)d_in[15];
    const float* fc2_w   = (const float*)d_in[16];
    const float* fc2_b   = (const float*)d_in[17];
    float* out = (float*)d_out;

    float *xa, *qkvb, *attn, *attn2, *xb;
    bf16 *ln, *att, *hbuf, *wbf;
    cudaGetSymbolAddress((void**)&xa,    g_xa);
    cudaGetSymbolAddress((void**)&ln,    g_ln);
    cudaGetSymbolAddress((void**)&qkvb,  g_qkv);
    cudaGetSymbolAddress((void**)&attn,  g_attn);
    cudaGetSymbolAddress((void**)&attn2, g_attn2);
    cudaGetSymbolAddress((void**)&att,   g_att);
    cudaGetSymbolAddress((void**)&xb,    g_xb);
    cudaGetSymbolAddress((void**)&hbuf,  g_h);
    cudaGetSymbolAddress((void**)&wbf,   g_wbf);

    dim3 cpeGrid(Ntok, Bsz);

    // convert weights to bf16 (cheap, deterministic, graph-capturable)
    cvt_w_kernel<<<(H3 * Cdim + 255) / 256, 256>>>(qkv_w,  wbf + W_QKV,  H3 * Cdim);
    cvt_w_kernel<<<(Cdim * Cdim + 255) / 256, 256>>>(proj_w, wbf + W_PROJ, Cdim * Cdim);
    cvt_w_kernel<<<(HID * Cdim + 255) / 256, 256>>>(fc1_w,  wbf + W_FC1,  HID * Cdim);
    cvt_w_kernel<<<(Cdim * HID + 255) / 256, 256>>>(fc2_w,  wbf + W_FC2,  Cdim * HID);

    // zero raw attention logits
    cudaMemsetAsync(attn, 0, (size_t)Bsz * NH * HD * HD * sizeof(float));

    // xa = cpe0(x); ln = LN1(xa) [bf16]
    cpe_ln_kernel<<<cpeGrid, Cdim>>>(x, cpe0_w, cpe0_b, norm1_g, norm1_b, xa, ln);
    // qkv = ln1 @ qkv_w^T  (fp32 out)
    gemm_bf16<0><<<dim3(H3 / BN, NT / BM), 256>>>(ln, wbf + W_QKV, nullptr, nullptr, qkvb, NT, H3, Cdim);
    // channel attention
    attnA_partial<<<dim3(Bsz * NH, 7), 256>>>(qkvb, attn);
    attnA_softmax<<<(Bsz * NH * HD + 255) / 256, 256>>>(attn, attn2);
    attnB_kernel<<<dim3(Bsz * NH, Ntok / 8), 384>>>(qkvb, attn2, att);
    // xb = xa + att @ proj_w^T + proj_b  (fp32 out)
    gemm_bf16<3><<<dim3(Cdim / BN, NT / BM), 256>>>(att, wbf + W_PROJ, proj_b, xa, xb, NT, Cdim, Cdim);
    // xc = cpe1(xb) -> xa ; ln = LN2(xc) [bf16]
    cpe_ln_kernel<<<cpeGrid, Cdim>>>(xb, cpe1_w, cpe1_b, norm2_g, norm2_b, xa, ln);
    // h = gelu(ln2 @ fc1^T + b1) [bf16 out]
    gemm_bf16<2><<<dim3(HID / BN, NT / BM), 256>>>(ln, wbf + W_FC1, fc1_b, nullptr, hbuf, NT, HID, Cdim);
    // out = xc + h @ fc2^T + b2 (fp32 out)
    gemm_bf16<3><<<dim3(Cdim / BN, NT / BM), 256>>>(hbuf, wbf + W_FC2, fc2_b, xa, out, NT, Cdim, HID);
}

// round 5
// speedup vs baseline: 3.2693x; 1.2569x over previous
#include <cuda_runtime.h>
#include <cuda_bf16.h>
#include <math.h>
#include <stdint.h>

// ---------------------------------------------------------------------------
// ChannelBlock: B=32, N=784 (28x28), C=384, heads=8, hd=48, MLP hidden=1536
// bf16 mma.sync GEMMs with ldmatrix fragment loads + 3-stage cp.async pipeline.
// (tcgen05 unavailable: harness PTX target is sm_103 without the 'a' features.)
// ---------------------------------------------------------------------------

#define Bsz   32
#define Ntok  784
#define Cdim  384
#define NT    (Bsz * Ntok)     // 25088
#define H3    (3 * Cdim)       // 1152
#define HID   1536
#define NH    8
#define HD    48

typedef __nv_bfloat16 bf16;

// scratch (static device memory; no allocation anywhere)
__device__ float g_xa  [(size_t)NT * Cdim];
__device__ bf16  g_ln  [(size_t)NT * Cdim];
__device__ float g_qkv [(size_t)NT * H3];
__device__ float g_attn[(size_t)Bsz * NH * HD * HD];   // raw logits (atomic acc)
__device__ float g_attn2[(size_t)Bsz * NH * HD * HD];  // softmaxed
__device__ bf16  g_att [(size_t)NT * Cdim];
__device__ float g_xb  [(size_t)NT * Cdim];
__device__ bf16  g_h   [(size_t)NT * HID];
// bf16 weights: qkv | proj | fc1 | fc2
#define W_QKV 0
#define W_PROJ (H3 * Cdim)
#define W_FC1  (W_PROJ + Cdim * Cdim)
#define W_FC2  (W_FC1 + HID * Cdim)
#define W_TOT  (W_FC2 + Cdim * HID)
__device__ bf16  g_wbf [(size_t)W_TOT];

__global__ void cvt_w_kernel(const float* __restrict__ in, bf16* __restrict__ out, int n)
{
    int i = blockIdx.x * blockDim.x + threadIdx.x;
    if (i < n) out[i] = __float2bfloat16(in[i]);
}

// ---------------------------------------------------------------------------
// Fused depthwise 3x3 conv (SAME) + residual + LayerNorm (bf16 LN output).
// ---------------------------------------------------------------------------
__global__ __launch_bounds__(Cdim)
void cpe_ln_kernel(const float* __restrict__ x,
                   const float* __restrict__ w,
                   const float* __restrict__ bias,
                   const float* __restrict__ lng,
                   const float* __restrict__ lnb,
                   float* __restrict__ y,
                   bf16* __restrict__ yln)
{
    int c = threadIdx.x;               // 0..383
    int n = blockIdx.x;                // 0..783
    int b = blockIdx.y;                // 0..31
    int i = n / 28, j = n % 28;

    const float* xb = x + (size_t)b * Ntok * Cdim + c;
    float acc = bias[c];
    const float* wc = w + c * 9;
#pragma unroll
    for (int di = -1; di <= 1; di++) {
        int ii = i + di;
        if (ii < 0 || ii >= 28) continue;
#pragma unroll
        for (int dj = -1; dj <= 1; dj++) {
            int jj = j + dj;
            if (jj < 0 || jj >= 28) continue;
            acc += wc[(di + 1) * 3 + (dj + 1)] * xb[(size_t)(ii * 28 + jj) * Cdim];
        }
    }
    size_t idx = ((size_t)b * Ntok + n) * Cdim + c;
    float val = x[idx] + acc;
    y[idx] = val;

    __shared__ float red[24];
    __shared__ float stats[2];
    float s = val, sq = val * val;
#pragma unroll
    for (int o = 16; o; o >>= 1) {
        s  += __shfl_xor_sync(0xffffffffu, s,  o);
        sq += __shfl_xor_sync(0xffffffffu, sq, o);
    }
    int warp = c >> 5, lane = c & 31;
    if (lane == 0) { red[warp] = s; red[12 + warp] = sq; }
    __syncthreads();
    if (c == 0) {
        float ts = 0.f, tq = 0.f;
#pragma unroll
        for (int k = 0; k < 12; k++) { ts += red[k]; tq += red[12 + k]; }
        float mean = ts * (1.f / Cdim);
        float var  = tq * (1.f / Cdim) - mean * mean;
        stats[0] = mean;
        stats[1] = rsqrtf(var + 1e-5f);
    }
    __syncthreads();
    float mean = stats[0], rs = stats[1];
    yln[idx] = __float2bfloat16((val - mean) * rs * lng[c] + lnb[c]);
}

// ---------------------------------------------------------------------------
// bf16 GEMM, NT form: C[m,n] = sum_k A[m,k] * W[n,k] (+ epilogue)
// BM=BN=128, BK=32, 256 threads (8 warps: 2m x 4n, warp tile 64x32).
// ldmatrix.x4 fragment loads from XOR-swizzled 64B smem rows;
// 3-stage cp.async pipeline (48KB static smem).
// EPI: 0 = none -> fp32 ; 2 = +bias + GELU -> bf16 ; 3 = +bias+res -> fp32
// ---------------------------------------------------------------------------
#define BM 128
#define BN 128
#define BK 32
#define STAGES 3
#define ASTG (BM * 64)                 // 8192 B per A stage (64B rows)
#define STG_BYTES (2 * ASTG)           // 16384 B (A + B)

__device__ __forceinline__ void cp16(unsigned saddr, const void* g)
{
    asm volatile("cp.async.cg.shared.global [%0], [%1], 16;\n" :: "r"(saddr), "l"(g));
}
__device__ __forceinline__ void ldsm4(uint32_t& r0, uint32_t& r1, uint32_t& r2,
                                      uint32_t& r3, uint32_t a)
{
    asm volatile("ldmatrix.sync.aligned.m8n8.x4.shared.b16 {%0,%1,%2,%3}, [%4];"
                 : "=r"(r0), "=r"(r1), "=r"(r2), "=r"(r3) : "r"(a));
}

template<int EPI>
__global__ __launch_bounds__(256)
void gemm_bf16(const bf16* __restrict__ A, const bf16* __restrict__ W,
               const float* __restrict__ bias, const float* __restrict__ res,
               void* __restrict__ Cout, int M, int N, int K)
{
    __shared__ alignas(128) char sm[STAGES * STG_BYTES];   // 48 KB
    uint32_t sb = (uint32_t)__cvta_generic_to_shared(sm);

    int tid = threadIdx.x;
    int w = tid >> 5, l = tid & 31;
    int row0 = blockIdx.y * BM;
    int col0 = blockIdx.x * BN;
    int wm = (w & 1) * 64;
    int wn = (w >> 1) * 32;
    int g = l >> 2, t = l & 3;

    // --- ldmatrix address precompute ---
    int jj  = l >> 3;                 // matrix index within x4
    int rlo = l & 7;
    // A: m0 rows+0 c0 | m1 rows+8 c0 | m2 rows+0 c0+1 | m3 rows+8 c0+1
    int rowA_in = (jj & 1) * 8 + rlo;
    int cA = jj >> 1;
    uint32_t aoff[4], axr[4];
#pragma unroll
    for (int mi = 0; mi < 4; mi++) {
        int rA = wm + mi * 16 + rowA_in;
        aoff[mi] = (uint32_t)rA * 64;
        axr[mi]  = (uint32_t)(((rA >> 1) & 3) << 4);
    }
    // B: m0 rows+0 c0 | m1 rows+0 c0+1 | m2 rows+8 c0 | m3 rows+8 c0+1
    int rowB_in = (jj >> 1) * 8 + rlo;
    int cB = jj & 1;
    uint32_t boff[2], bxr[2];
#pragma unroll
    for (int p = 0; p < 2; p++) {
        int rB = wn + p * 16 + rowB_in;
        boff[p] = (uint32_t)(ASTG + rB * 64);
        bxr[p]  = (uint32_t)(((rB >> 1) & 3) << 4);
    }

    float acc[4][4][4];
#pragma unroll
    for (int mi = 0; mi < 4; mi++)
#pragma unroll
        for (int ni = 0; ni < 4; ni++)
#pragma unroll
            for (int r = 0; r < 4; r++) acc[mi][ni][r] = 0.f;

    const int NS = K / BK;

    // loader: 512 16B chunks per matrix per stage; 2 per thread per matrix
    auto load_stage = [&](int s) {
        uint32_t tb = sb + (s % STAGES) * STG_BYTES;
        int kt = s * BK;
        const bf16* Ab = A + (size_t)row0 * K + kt;
        const bf16* Wb = W + (size_t)col0 * K + kt;
#pragma unroll
        for (int i = 0; i < 2; i++) {
            int id = tid + i * 256;        // 0..511
            int r = id >> 2, c = id & 3;
            int cs = c ^ ((r >> 1) & 3);
            cp16(tb + r * 64 + cs * 16, Ab + (size_t)r * K + c * 8);
            cp16(tb + ASTG + r * 64 + cs * 16, Wb + (size_t)r * K + c * 8);
        }
    };

    // prologue: stages 0..STAGES-2
    load_stage(0);
    asm volatile("cp.async.commit_group;\n");
    load_stage(1);
    asm volatile("cp.async.commit_group;\n");

    for (int s = 0; s < NS; s++) {
        asm volatile("cp.async.wait_group 1;\n");
        __syncthreads();

        if (s + STAGES - 1 < NS) load_stage(s + STAGES - 1);
        asm volatile("cp.async.commit_group;\n");   // unconditional: keeps count

        uint32_t stb = sb + (s % STAGES) * STG_BYTES;
#pragma unroll
        for (int kk = 0; kk < 2; kk++) {
            uint32_t c0 = kk * 2;       // 16B chunk base within 64B row
            uint32_t af[4][4];
#pragma unroll
            for (int mi = 0; mi < 4; mi++)
                ldsm4(af[mi][0], af[mi][1], af[mi][2], af[mi][3],
                      stb + aoff[mi] + ((((c0 + cA) << 4)) ^ axr[mi]));
            uint32_t bq[2][4];
#pragma unroll
            for (int p = 0; p < 2; p++)
                ldsm4(bq[p][0], bq[p][1], bq[p][2], bq[p][3],
                      stb + boff[p] + ((((c0 + cB) << 4)) ^ bxr[p]));

#pragma unroll
            for (int mi = 0; mi < 4; mi++)
#pragma unroll
                for (int ni = 0; ni < 4; ni++) {
                    int p = ni >> 1, q = ni & 1;
                    asm volatile(
                        "mma.sync.aligned.m16n8k16.row.col.f32.bf16.bf16.f32 "
                        "{%0,%1,%2,%3}, {%4,%5,%6,%7}, {%8,%9}, {%0,%1,%2,%3};"
                        : "+f"(acc[mi][ni][0]), "+f"(acc[mi][ni][1]),
                          "+f"(acc[mi][ni][2]), "+f"(acc[mi][ni][3])
                        : "r"(af[mi][0]), "r"(af[mi][1]), "r"(af[mi][2]), "r"(af[mi][3]),
                          "r"(bq[p][2 * q]), "r"(bq[p][2 * q + 1]));
                }
        }
    }

    // epilogue: c0=C[g][2t], c1=C[g][2t+1], c2=C[g+8][2t], c3=C[g+8][2t+1]
#pragma unroll
    for (int mi = 0; mi < 4; mi++) {
#pragma unroll
        for (int ni = 0; ni < 4; ni++) {
#pragma unroll
            for (int r = 0; r < 4; r++) {
                int row = row0 + wm + mi * 16 + g + (r >> 1) * 8;
                int col = col0 + wn + ni * 8 + 2 * t + (r & 1);
                size_t idx = (size_t)row * N + col;
                float v = acc[mi][ni][r];
                if (EPI == 0) {
                    ((float*)Cout)[idx] = v;
                } else if (EPI == 2) {
                    v += bias[col];
                    v = 0.5f * v * (1.f + erff(v * 0.7071067811865475f));
                    ((bf16*)Cout)[idx] = __float2bfloat16(v);
                } else if (EPI == 3) {
                    v += bias[col] + res[idx];
                    ((float*)Cout)[idx] = v;
                }
            }
        }
    }
}

// ---------------------------------------------------------------------------
// Channel attention stage A (partial): accumulate (k*s)^T v into raw logits.
// ---------------------------------------------------------------------------
__global__ __launch_bounds__(256)
void attnA_partial(const float* __restrict__ qkv, float* __restrict__ raw)
{
    __shared__ float ks[32][49];
    __shared__ float vs[32][49];

    int bh = blockIdx.x;
    int b = bh >> 3, h = bh & 7;
    int nstart = blockIdx.y * 112;
    int nend   = nstart + 112;
    int tid = threadIdx.x;
    int tx = tid & 15, ty = tid >> 4;
    const float scale = 0.14433756729740643f;   // 48^-0.5

    float acc[3][3] = {{0.f,0.f,0.f},{0.f,0.f,0.f},{0.f,0.f,0.f}};
    const float* base = qkv + (size_t)b * Ntok * H3 + h * HD;

    for (int n0 = nstart; n0 < nend; n0 += 32) {
        int cnt = min(32, nend - n0);
        for (int idx = tid; idx < cnt * HD; idx += 256) {
            int nn = idx / HD, d = idx % HD;
            const float* r = base + (size_t)(n0 + nn) * H3;
            ks[nn][d] = r[Cdim + d] * scale;   // k
            vs[nn][d] = r[2 * Cdim + d];       // v
        }
        __syncthreads();
        for (int nn = 0; nn < cnt; nn++) {
            float rk[3], rv[3];
#pragma unroll
            for (int i = 0; i < 3; i++) { rk[i] = ks[nn][ty * 3 + i]; rv[i] = vs[nn][tx * 3 + i]; }
#pragma unroll
            for (int i = 0; i < 3; i++)
#pragma unroll
                for (int j = 0; j < 3; j++)
                    acc[i][j] = fmaf(rk[i], rv[j], acc[i][j]);
        }
        __syncthreads();
    }

    float* o = raw + (size_t)bh * (HD * HD);
#pragma unroll
    for (int i = 0; i < 3; i++)
#pragma unroll
        for (int j = 0; j < 3; j++)
            atomicAdd(&o[(ty * 3 + i) * HD + tx * 3 + j], acc[i][j]);
}

// softmax over last dim of 48x48 logits; one thread per (bh, d) row.
__global__ __launch_bounds__(256)
void attnA_softmax(const float* __restrict__ raw, float* __restrict__ attn_out)
{
    int idx = blockIdx.x * 256 + threadIdx.x;
    if (idx >= Bsz * NH * HD) return;
    const float* r = raw + (size_t)idx * HD;
    float* o = attn_out + (size_t)idx * HD;
    float m = -1e30f;
#pragma unroll
    for (int e = 0; e < HD; e++) m = fmaxf(m, r[e]);
    float s = 0.f;
    float tv[HD];
#pragma unroll
    for (int e = 0; e < HD; e++) { tv[e] = expf(r[e] - m); s += tv[e]; }
    float inv = 1.f / s;
#pragma unroll
    for (int e = 0; e < HD; e++) o[e] = tv[e] * inv;
}

// ---------------------------------------------------------------------------
// Channel attention stage B: out[b,n,h*48+d] = sum_e attn[d,e] * q[b,n,h,e]
// Writes bf16 (feeds proj GEMM).
// ---------------------------------------------------------------------------
__global__ __launch_bounds__(384)
void attnB_kernel(const float* __restrict__ qkv, const float* __restrict__ attn,
                  bf16* __restrict__ out)
{
    __shared__ float at[48 * 49];
    __shared__ float qs[8][48];

    int bh = blockIdx.x;
    int b = bh >> 3, h = bh & 7;
    int n0 = blockIdx.y * 8;
    int tid = threadIdx.x;

    const float* ab = attn + (size_t)bh * (HD * HD);
    for (int idx = tid; idx < HD * HD; idx += 384) {
        int d = idx / HD, e = idx % HD;
        at[d * 49 + e] = ab[idx];
    }
    int nl = tid / HD;
    int d  = tid % HD;
    qs[nl][d] = qkv[((size_t)b * Ntok + n0 + nl) * H3 + h * HD + d];  // q
    __syncthreads();

    float acc = 0.f;
#pragma unroll
    for (int e = 0; e < HD; e++)
        acc = fmaf(at[d * 49 + e], qs[nl][e], acc);

    out[((size_t)b * Ntok + n0 + nl) * Cdim + h * HD + d] = __float2bfloat16(acc);
}

// ---------------------------------------------------------------------------
// Launch
// ---------------------------------------------------------------------------
extern "C" void kernel_launch(void* const* d_in, const int* in_sizes, int n_in,
                              void* d_out, int out_size)
{
    const float* x       = (const float*)d_in[0];
    const float* cpe0_w  = (const float*)d_in[3];
    const float* cpe0_b  = (const float*)d_in[4];
    const float* cpe1_w  = (const float*)d_in[5];
    const float* cpe1_b  = (const float*)d_in[6];
    const float* norm1_g = (const float*)d_in[7];
    const float* norm1_b = (const float*)d_in[8];
    const float* qkv_w   = (const float*)d_in[9];
    const float* proj_w  = (const float*)d_in[10];
    const float* proj_b  = (const float*)d_in[11];
    const float* norm2_g = (const float*)d_in[12];
    const float* norm2_b = (const float*)d_in[13];
    const float* fc1_w   = (const float*)d_in[14];
    const float* fc1_b   = (const float*)d_in[15];
    const float* fc2_w   = (const float*)d_in[16];
    const float* fc2_b   = (const float*)d_in[17];
    float* out = (float*)d_out;

    float *xa, *qkvb, *attn, *attn2, *xb;
    bf16 *ln, *att, *hbuf, *wbf;
    cudaGetSymbolAddress((void**)&xa,    g_xa);
    cudaGetSymbolAddress((void**)&ln,    g_ln);
    cudaGetSymbolAddress((void**)&qkvb,  g_qkv);
    cudaGetSymbolAddress((void**)&attn,  g_attn);
    cudaGetSymbolAddress((void**)&attn2, g_attn2);
    cudaGetSymbolAddress((void**)&att,   g_att);
    cudaGetSymbolAddress((void**)&xb,    g_xb);
    cudaGetSymbolAddress((void**)&hbuf,  g_h);
    cudaGetSymbolAddress((void**)&wbf,   g_wbf);

    dim3 cpeGrid(Ntok, Bsz);

    // convert weights to bf16 (cheap, deterministic, graph-capturable)
    cvt_w_kernel<<<(H3 * Cdim + 255) / 256, 256>>>(qkv_w,  wbf + W_QKV,  H3 * Cdim);
    cvt_w_kernel<<<(Cdim * Cdim + 255) / 256, 256>>>(proj_w, wbf + W_PROJ, Cdim * Cdim);
    cvt_w_kernel<<<(HID * Cdim + 255) / 256, 256>>>(fc1_w,  wbf + W_FC1,  HID * Cdim);
    cvt_w_kernel<<<(Cdim * HID + 255) / 256, 256>>>(fc2_w,  wbf + W_FC2,  Cdim * HID);

    // zero raw attention logits
    cudaMemsetAsync(attn, 0, (size_t)Bsz * NH * HD * HD * sizeof(float));

    // xa = cpe0(x); ln = LN1(xa) [bf16]
    cpe_ln_kernel<<<cpeGrid, Cdim>>>(x, cpe0_w, cpe0_b, norm1_g, norm1_b, xa, ln);
    // qkv = ln1 @ qkv_w^T  (fp32 out)
    gemm_bf16<0><<<dim3(H3 / BN, NT / BM), 256>>>(ln, wbf + W_QKV, nullptr, nullptr, qkvb, NT, H3, Cdim);
    // channel attention
    attnA_partial<<<dim3(Bsz * NH, 7), 256>>>(qkvb, attn);
    attnA_softmax<<<(Bsz * NH * HD + 255) / 256, 256>>>(attn, attn2);
    attnB_kernel<<<dim3(Bsz * NH, Ntok / 8), 384>>>(qkvb, attn2, att);
    // xb = xa + att @ proj_w^T + proj_b  (fp32 out)
    gemm_bf16<3><<<dim3(Cdim / BN, NT / BM), 256>>>(att, wbf + W_PROJ, proj_b, xa, xb, NT, Cdim, Cdim);
    // xc = cpe1(xb) -> xa ; ln = LN2(xc) [bf16]
    cpe_ln_kernel<<<cpeGrid, Cdim>>>(xb, cpe1_w, cpe1_b, norm2_g, norm2_b, xa, ln);
    // h = gelu(ln2 @ fc1^T + b1) [bf16 out]
    gemm_bf16<2><<<dim3(HID / BN, NT / BM), 256>>>(ln, wbf + W_FC1, fc1_b, nullptr, hbuf, NT, HID, Cdim);
    // out = xc + h @ fc2^T + b2 (fp32 out)
    gemm_bf16<3><<<dim3(Cdim / BN, NT / BM), 256>>>(hbuf, wbf + W_FC2, fc2_b, xa, out, NT, Cdim, HID);
}

// round 6
// speedup vs baseline: 4.1259x; 1.2620x over previous
#include <cuda_runtime.h>
#include <cuda_bf16.h>
#include <math.h>
#include <stdint.h>

// ---------------------------------------------------------------------------
// ChannelBlock: B=32, N=784 (28x28), C=384, heads=8, hd=48, MLP hidden=1536
// bf16 mma.sync GEMMs: ldmatrix fragments, 3-stage cp.async pipeline,
// K templated (full unroll), batched LDSM issue, float2 epilogue.
// ---------------------------------------------------------------------------

#define Bsz   32
#define Ntok  784
#define Cdim  384
#define NT    (Bsz * Ntok)     // 25088
#define H3    (3 * Cdim)       // 1152
#define HID   1536
#define NH    8
#define HD    48

typedef __nv_bfloat16 bf16;

// scratch (static device memory; no allocation anywhere)
__device__ float g_xa  [(size_t)NT * Cdim];
__device__ bf16  g_ln  [(size_t)NT * Cdim];
__device__ float g_qkv [(size_t)NT * H3];
__device__ float g_attn[(size_t)Bsz * NH * HD * HD];   // raw logits (atomic acc)
__device__ float g_attn2[(size_t)Bsz * NH * HD * HD];  // softmaxed
__device__ bf16  g_att [(size_t)NT * Cdim];
__device__ float g_xb  [(size_t)NT * Cdim];
__device__ bf16  g_h   [(size_t)NT * HID];
// bf16 weights: qkv | proj | fc1 | fc2
#define W_QKV 0
#define W_PROJ (H3 * Cdim)
#define W_FC1  (W_PROJ + Cdim * Cdim)
#define W_FC2  (W_FC1 + HID * Cdim)
#define W_TOT  (W_FC2 + Cdim * HID)
__device__ bf16  g_wbf [(size_t)W_TOT];

__global__ void cvt_w_kernel(const float* __restrict__ in, bf16* __restrict__ out, int n)
{
    int i = blockIdx.x * blockDim.x + threadIdx.x;
    if (i < n) out[i] = __float2bfloat16(in[i]);
}

// ---------------------------------------------------------------------------
// Fused depthwise 3x3 conv (SAME) + residual + LayerNorm (bf16 LN output).
// ---------------------------------------------------------------------------
__global__ __launch_bounds__(Cdim)
void cpe_ln_kernel(const float* __restrict__ x,
                   const float* __restrict__ w,
                   const float* __restrict__ bias,
                   const float* __restrict__ lng,
                   const float* __restrict__ lnb,
                   float* __restrict__ y,
                   bf16* __restrict__ yln)
{
    int c = threadIdx.x;               // 0..383
    int n = blockIdx.x;                // 0..783
    int b = blockIdx.y;                // 0..31
    int i = n / 28, j = n % 28;

    const float* xb = x + (size_t)b * Ntok * Cdim + c;
    float acc = bias[c];
    const float* wc = w + c * 9;
#pragma unroll
    for (int di = -1; di <= 1; di++) {
        int ii = i + di;
        if (ii < 0 || ii >= 28) continue;
#pragma unroll
        for (int dj = -1; dj <= 1; dj++) {
            int jj = j + dj;
            if (jj < 0 || jj >= 28) continue;
            acc += wc[(di + 1) * 3 + (dj + 1)] * xb[(size_t)(ii * 28 + jj) * Cdim];
        }
    }
    size_t idx = ((size_t)b * Ntok + n) * Cdim + c;
    float val = x[idx] + acc;
    y[idx] = val;

    __shared__ float red[24];
    __shared__ float stats[2];
    float s = val, sq = val * val;
#pragma unroll
    for (int o = 16; o; o >>= 1) {
        s  += __shfl_xor_sync(0xffffffffu, s,  o);
        sq += __shfl_xor_sync(0xffffffffu, sq, o);
    }
    int warp = c >> 5, lane = c & 31;
    if (lane == 0) { red[warp] = s; red[12 + warp] = sq; }
    __syncthreads();
    if (c == 0) {
        float ts = 0.f, tq = 0.f;
#pragma unroll
        for (int k = 0; k < 12; k++) { ts += red[k]; tq += red[12 + k]; }
        float mean = ts * (1.f / Cdim);
        float var  = tq * (1.f / Cdim) - mean * mean;
        stats[0] = mean;
        stats[1] = rsqrtf(var + 1e-5f);
    }
    __syncthreads();
    float mean = stats[0], rs = stats[1];
    yln[idx] = __float2bfloat16((val - mean) * rs * lng[c] + lnb[c]);
}

// ---------------------------------------------------------------------------
// bf16 GEMM, NT form: C[m,n] = sum_k A[m,k] * W[n,k] (+ epilogue)
// BM=BN=128, BK=32, 256 threads (8 warps: 2m x 4n, warp tile 64x32).
// K is a template parameter -> fully unrolled stage loop.
// EPI: 0 = none -> fp32 ; 2 = +bias + GELU -> bf16 ; 3 = +bias+res -> fp32
// ---------------------------------------------------------------------------
#define BM 128
#define BN 128
#define BK 32
#define STAGES 3
#define ASTG (BM * 64)                 // 8192 B per A stage (64B rows)
#define STG_BYTES (2 * ASTG)           // 16384 B (A + B)

__device__ __forceinline__ void cp16(unsigned saddr, const void* g)
{
    asm volatile("cp.async.cg.shared.global [%0], [%1], 16;\n" :: "r"(saddr), "l"(g));
}
__device__ __forceinline__ void ldsm4(uint32_t& r0, uint32_t& r1, uint32_t& r2,
                                      uint32_t& r3, uint32_t a)
{
    asm volatile("ldmatrix.sync.aligned.m8n8.x4.shared.b16 {%0,%1,%2,%3}, [%4];"
                 : "=r"(r0), "=r"(r1), "=r"(r2), "=r"(r3) : "r"(a));
}

template<int EPI, int K>
__global__ __launch_bounds__(256)
void gemm_bf16(const bf16* __restrict__ A, const bf16* __restrict__ W,
               const float* __restrict__ bias, const float* __restrict__ res,
               void* __restrict__ Cout, int M, int N)
{
    __shared__ alignas(128) char sm[STAGES * STG_BYTES];   // 48 KB
    uint32_t sb = (uint32_t)__cvta_generic_to_shared(sm);

    int tid = threadIdx.x;
    int w = tid >> 5, l = tid & 31;
    int row0 = blockIdx.y * BM;
    int col0 = blockIdx.x * BN;
    int wm = (w & 1) * 64;
    int wn = (w >> 1) * 32;
    int g = l >> 2, t = l & 3;

    // --- ldmatrix address precompute ---
    int jj  = l >> 3;                 // matrix index within x4
    int rlo = l & 7;
    int rowA_in = (jj & 1) * 8 + rlo;
    int cA = jj >> 1;
    uint32_t aoff[4], axr[4];
#pragma unroll
    for (int mi = 0; mi < 4; mi++) {
        int rA = wm + mi * 16 + rowA_in;
        aoff[mi] = (uint32_t)rA * 64;
        axr[mi]  = (uint32_t)(((rA >> 1) & 3) << 4);
    }
    int rowB_in = (jj >> 1) * 8 + rlo;
    int cB = jj & 1;
    uint32_t boff[2], bxr[2];
#pragma unroll
    for (int p = 0; p < 2; p++) {
        int rB = wn + p * 16 + rowB_in;
        boff[p] = (uint32_t)(ASTG + rB * 64);
        bxr[p]  = (uint32_t)(((rB >> 1) & 3) << 4);
    }

    float acc[4][4][4];
#pragma unroll
    for (int mi = 0; mi < 4; mi++)
#pragma unroll
        for (int ni = 0; ni < 4; ni++)
#pragma unroll
            for (int r = 0; r < 4; r++) acc[mi][ni][r] = 0.f;

    constexpr int NS = K / BK;

    // loader: 512 16B chunks per matrix per stage; 2 per thread per matrix
    auto load_stage = [&](int s) {
        uint32_t tb = sb + (s % STAGES) * STG_BYTES;
        int kt = s * BK;
        const bf16* Ab = A + (size_t)row0 * K + kt;
        const bf16* Wb = W + (size_t)col0 * K + kt;
#pragma unroll
        for (int i = 0; i < 2; i++) {
            int id = tid + i * 256;        // 0..511
            int r = id >> 2, c = id & 3;
            int cs = c ^ ((r >> 1) & 3);
            cp16(tb + r * 64 + cs * 16, Ab + (size_t)r * K + c * 8);
            cp16(tb + ASTG + r * 64 + cs * 16, Wb + (size_t)r * K + c * 8);
        }
    };

    load_stage(0);
    asm volatile("cp.async.commit_group;\n");
    load_stage(1);
    asm volatile("cp.async.commit_group;\n");

#pragma unroll
    for (int s = 0; s < NS; s++) {
        asm volatile("cp.async.wait_group 1;\n");
        __syncthreads();

        if (s + STAGES - 1 < NS) load_stage(s + STAGES - 1);
        asm volatile("cp.async.commit_group;\n");   // unconditional: keeps count

        uint32_t stb = sb + (s % STAGES) * STG_BYTES;

        // ---- issue ALL fragment loads for the stage first (12 LDSM) ----
        uint32_t af[2][4][4], bq[2][2][4];
#pragma unroll
        for (int kk = 0; kk < 2; kk++) {
            uint32_t c0 = kk * 2;
#pragma unroll
            for (int mi = 0; mi < 4; mi++)
                ldsm4(af[kk][mi][0], af[kk][mi][1], af[kk][mi][2], af[kk][mi][3],
                      stb + aoff[mi] + ((((c0 + cA) << 4)) ^ axr[mi]));
#pragma unroll
            for (int p = 0; p < 2; p++)
                ldsm4(bq[kk][p][0], bq[kk][p][1], bq[kk][p][2], bq[kk][p][3],
                      stb + boff[p] + ((((c0 + cB) << 4)) ^ bxr[p]));
        }
        // ---- then both MMA groups (32 HMMA) ----
#pragma unroll
        for (int kk = 0; kk < 2; kk++)
#pragma unroll
            for (int mi = 0; mi < 4; mi++)
#pragma unroll
                for (int ni = 0; ni < 4; ni++) {
                    int p = ni >> 1, q = ni & 1;
                    asm volatile(
                        "mma.sync.aligned.m16n8k16.row.col.f32.bf16.bf16.f32 "
                        "{%0,%1,%2,%3}, {%4,%5,%6,%7}, {%8,%9}, {%0,%1,%2,%3};"
                        : "+f"(acc[mi][ni][0]), "+f"(acc[mi][ni][1]),
                          "+f"(acc[mi][ni][2]), "+f"(acc[mi][ni][3])
                        : "r"(af[kk][mi][0]), "r"(af[kk][mi][1]),
                          "r"(af[kk][mi][2]), "r"(af[kk][mi][3]),
                          "r"(bq[kk][p][2 * q]), "r"(bq[kk][p][2 * q + 1]));
                }
    }

    // ---- epilogue: float2 / bfloat162 stores (cols 2t,2t+1 adjacent) ----
#pragma unroll
    for (int mi = 0; mi < 4; mi++) {
#pragma unroll
        for (int ni = 0; ni < 4; ni++) {
            int col = col0 + wn + ni * 8 + 2 * t;
#pragma unroll
            for (int half = 0; half < 2; half++) {
                int row = row0 + wm + mi * 16 + g + half * 8;
                size_t idx = (size_t)row * N + col;
                float v0 = acc[mi][ni][2 * half];
                float v1 = acc[mi][ni][2 * half + 1];
                if (EPI == 0) {
                    *(float2*)&((float*)Cout)[idx] = make_float2(v0, v1);
                } else if (EPI == 2) {
                    float2 bv = *(const float2*)&bias[col];
                    v0 += bv.x; v1 += bv.y;
                    v0 = 0.5f * v0 * (1.f + erff(v0 * 0.7071067811865475f));
                    v1 = 0.5f * v1 * (1.f + erff(v1 * 0.7071067811865475f));
                    __nv_bfloat162 pk;
                    pk.x = __float2bfloat16(v0);
                    pk.y = __float2bfloat16(v1);
                    *(__nv_bfloat162*)&((bf16*)Cout)[idx] = pk;
                } else {
                    float2 bv = *(const float2*)&bias[col];
                    float2 rv = *(const float2*)&res[idx];
                    v0 += bv.x + rv.x; v1 += bv.y + rv.y;
                    *(float2*)&((float*)Cout)[idx] = make_float2(v0, v1);
                }
            }
        }
    }
}

// ---------------------------------------------------------------------------
// Channel attention stage A (partial): accumulate (k*s)^T v into raw logits.
// ---------------------------------------------------------------------------
__global__ __launch_bounds__(256)
void attnA_partial(const float* __restrict__ qkv, float* __restrict__ raw)
{
    __shared__ float ks[32][49];
    __shared__ float vs[32][49];

    int bh = blockIdx.x;
    int b = bh >> 3, h = bh & 7;
    int nstart = blockIdx.y * 112;
    int nend   = nstart + 112;
    int tid = threadIdx.x;
    int tx = tid & 15, ty = tid >> 4;
    const float scale = 0.14433756729740643f;   // 48^-0.5

    float acc[3][3] = {{0.f,0.f,0.f},{0.f,0.f,0.f},{0.f,0.f,0.f}};
    const float* base = qkv + (size_t)b * Ntok * H3 + h * HD;

    for (int n0 = nstart; n0 < nend; n0 += 32) {
        int cnt = min(32, nend - n0);
        for (int idx = tid; idx < cnt * HD; idx += 256) {
            int nn = idx / HD, d = idx % HD;
            const float* r = base + (size_t)(n0 + nn) * H3;
            ks[nn][d] = r[Cdim + d] * scale;   // k
            vs[nn][d] = r[2 * Cdim + d];       // v
        }
        __syncthreads();
        for (int nn = 0; nn < cnt; nn++) {
            float rk[3], rv[3];
#pragma unroll
            for (int i = 0; i < 3; i++) { rk[i] = ks[nn][ty * 3 + i]; rv[i] = vs[nn][tx * 3 + i]; }
#pragma unroll
            for (int i = 0; i < 3; i++)
#pragma unroll
                for (int j = 0; j < 3; j++)
                    acc[i][j] = fmaf(rk[i], rv[j], acc[i][j]);
        }
        __syncthreads();
    }

    float* o = raw + (size_t)bh * (HD * HD);
#pragma unroll
    for (int i = 0; i < 3; i++)
#pragma unroll
        for (int j = 0; j < 3; j++)
            atomicAdd(&o[(ty * 3 + i) * HD + tx * 3 + j], acc[i][j]);
}

// softmax over last dim of 48x48 logits; one thread per (bh, d) row.
__global__ __launch_bounds__(256)
void attnA_softmax(const float* __restrict__ raw, float* __restrict__ attn_out)
{
    int idx = blockIdx.x * 256 + threadIdx.x;
    if (idx >= Bsz * NH * HD) return;
    const float* r = raw + (size_t)idx * HD;
    float* o = attn_out + (size_t)idx * HD;
    float m = -1e30f;
#pragma unroll
    for (int e = 0; e < HD; e++) m = fmaxf(m, r[e]);
    float s = 0.f;
    float tv[HD];
#pragma unroll
    for (int e = 0; e < HD; e++) { tv[e] = expf(r[e] - m); s += tv[e]; }
    float inv = 1.f / s;
#pragma unroll
    for (int e = 0; e < HD; e++) o[e] = tv[e] * inv;
}

// ---------------------------------------------------------------------------
// Channel attention stage B: out[b,n,h*48+d] = sum_e attn[d,e] * q[b,n,h,e]
// ---------------------------------------------------------------------------
__global__ __launch_bounds__(384)
void attnB_kernel(const float* __restrict__ qkv, const float* __restrict__ attn,
                  bf16* __restrict__ out)
{
    __shared__ float at[48 * 49];
    __shared__ float qs[8][48];

    int bh = blockIdx.x;
    int b = bh >> 3, h = bh & 7;
    int n0 = blockIdx.y * 8;
    int tid = threadIdx.x;

    const float* ab = attn + (size_t)bh * (HD * HD);
    for (int idx = tid; idx < HD * HD; idx += 384) {
        int d = idx / HD, e = idx % HD;
        at[d * 49 + e] = ab[idx];
    }
    int nl = tid / HD;
    int d  = tid % HD;
    qs[nl][d] = qkv[((size_t)b * Ntok + n0 + nl) * H3 + h * HD + d];  // q
    __syncthreads();

    float acc = 0.f;
#pragma unroll
    for (int e = 0; e < HD; e++)
        acc = fmaf(at[d * 49 + e], qs[nl][e], acc);

    out[((size_t)b * Ntok + n0 + nl) * Cdim + h * HD + d] = __float2bfloat16(acc);
}

// ---------------------------------------------------------------------------
// Launch
// ---------------------------------------------------------------------------
extern "C" void kernel_launch(void* const* d_in, const int* in_sizes, int n_in,
                              void* d_out, int out_size)
{
    const float* x       = (const float*)d_in[0];
    const float* cpe0_w  = (const float*)d_in[3];
    const float* cpe0_b  = (const float*)d_in[4];
    const float* cpe1_w  = (const float*)d_in[5];
    const float* cpe1_b  = (const float*)d_in[6];
    const float* norm1_g = (const float*)d_in[7];
    const float* norm1_b = (const float*)d_in[8];
    const float* qkv_w   = (const float*)d_in[9];
    const float* proj_w  = (const float*)d_in[10];
    const float* proj_b  = (const float*)d_in[11];
    const float* norm2_g = (const float*)d_in[12];
    const float* norm2_b = (const float*)d_in[13];
    const float* fc1_w   = (const float*)d_in[14];
    const float* fc1_b   = (const float*)d_in[15];
    const float* fc2_w   = (const float*)d_in[16];
    const float* fc2_b   = (const float*)d_in[17];
    float* out = (float*)d_out;

    float *xa, *qkvb, *attn, *attn2, *xb;
    bf16 *ln, *att, *hbuf, *wbf;
    cudaGetSymbolAddress((void**)&xa,    g_xa);
    cudaGetSymbolAddress((void**)&ln,    g_ln);
    cudaGetSymbolAddress((void**)&qkvb,  g_qkv);
    cudaGetSymbolAddress((void**)&attn,  g_attn);
    cudaGetSymbolAddress((void**)&attn2, g_attn2);
    cudaGetSymbolAddress((void**)&att,   g_att);
    cudaGetSymbolAddress((void**)&xb,    g_xb);
    cudaGetSymbolAddress((void**)&hbuf,  g_h);
    cudaGetSymbolAddress((void**)&wbf,   g_wbf);

    dim3 cpeGrid(Ntok, Bsz);

    // convert weights to bf16 (cheap, deterministic, graph-capturable)
    cvt_w_kernel<<<(H3 * Cdim + 255) / 256, 256>>>(qkv_w,  wbf + W_QKV,  H3 * Cdim);
    cvt_w_kernel<<<(Cdim * Cdim + 255) / 256, 256>>>(proj_w, wbf + W_PROJ, Cdim * Cdim);
    cvt_w_kernel<<<(HID * Cdim + 255) / 256, 256>>>(fc1_w,  wbf + W_FC1,  HID * Cdim);
    cvt_w_kernel<<<(Cdim * HID + 255) / 256, 256>>>(fc2_w,  wbf + W_FC2,  Cdim * HID);

    // zero raw attention logits
    cudaMemsetAsync(attn, 0, (size_t)Bsz * NH * HD * HD * sizeof(float));

    // xa = cpe0(x); ln = LN1(xa) [bf16]
    cpe_ln_kernel<<<cpeGrid, Cdim>>>(x, cpe0_w, cpe0_b, norm1_g, norm1_b, xa, ln);
    // qkv = ln1 @ qkv_w^T  (fp32 out)
    gemm_bf16<0, Cdim><<<dim3(H3 / BN, NT / BM), 256>>>(ln, wbf + W_QKV, nullptr, nullptr, qkvb, NT, H3);
    // channel attention
    attnA_partial<<<dim3(Bsz * NH, 7), 256>>>(qkvb, attn);
    attnA_softmax<<<(Bsz * NH * HD + 255) / 256, 256>>>(attn, attn2);
    attnB_kernel<<<dim3(Bsz * NH, Ntok / 8), 384>>>(qkvb, attn2, att);
    // xb = xa + att @ proj_w^T + proj_b  (fp32 out)
    gemm_bf16<3, Cdim><<<dim3(Cdim / BN, NT / BM), 256>>>(att, wbf + W_PROJ, proj_b, xa, xb, NT, Cdim);
    // xc = cpe1(xb) -> xa ; ln = LN2(xc) [bf16]
    cpe_ln_kernel<<<cpeGrid, Cdim>>>(xb, cpe1_w, cpe1_b, norm2_g, norm2_b, xa, ln);
    // h = gelu(ln2 @ fc1^T + b1) [bf16 out]
    gemm_bf16<2, Cdim><<<dim3(HID / BN, NT / BM), 256>>>(ln, wbf + W_FC1, fc1_b, nullptr, hbuf, NT, HID);
    // out = xc + h @ fc2^T + b2 (fp32 out)
    gemm_bf16<3, HID><<<dim3(Cdim / BN, NT / BM), 256>>>(hbuf, wbf + W_FC2, fc2_b, xa, out, NT, Cdim);
}

// round 7
// speedup vs baseline: 4.1882x; 1.0151x over previous
#include <cuda_runtime.h>
#include <cuda_bf16.h>
#include <math.h>
#include <stdint.h>

// ---------------------------------------------------------------------------
// ChannelBlock: B=32, N=784 (28x28), C=384, heads=8, hd=48, MLP hidden=1536
// bf16 mma.sync GEMMs: ldmatrix fragments, 3-stage cp.async pipeline,
// K templated, 2 CTAs/SM (128-reg cap, single-buffer fragments).
// ---------------------------------------------------------------------------

#define Bsz   32
#define Ntok  784
#define Cdim  384
#define NT    (Bsz * Ntok)     // 25088
#define H3    (3 * Cdim)       // 1152
#define HID   1536
#define NH    8
#define HD    48

typedef __nv_bfloat16 bf16;

// scratch (static device memory; no allocation anywhere)
__device__ float g_xa  [(size_t)NT * Cdim];
__device__ bf16  g_ln  [(size_t)NT * Cdim];
__device__ float g_qkv [(size_t)NT * H3];
__device__ float g_attn[(size_t)Bsz * NH * HD * HD];   // raw logits (atomic acc)
__device__ float g_attn2[(size_t)Bsz * NH * HD * HD];  // softmaxed
__device__ bf16  g_att [(size_t)NT * Cdim];
__device__ float g_xb  [(size_t)NT * Cdim];
__device__ bf16  g_h   [(size_t)NT * HID];
// bf16 weights: qkv | proj | fc1 | fc2
#define W_QKV 0
#define W_PROJ (H3 * Cdim)
#define W_FC1  (W_PROJ + Cdim * Cdim)
#define W_FC2  (W_FC1 + HID * Cdim)
#define W_TOT  (W_FC2 + Cdim * HID)
__device__ bf16  g_wbf [(size_t)W_TOT];

// single launch: convert all 4 weight matrices to bf16
__global__ void cvt_all_kernel(const float* __restrict__ qkv_w,
                               const float* __restrict__ proj_w,
                               const float* __restrict__ fc1_w,
                               const float* __restrict__ fc2_w,
                               bf16* __restrict__ out)
{
    int i = blockIdx.x * blockDim.x + threadIdx.x;
    if (i >= W_TOT) return;
    float v;
    if (i < W_PROJ)      v = qkv_w[i];
    else if (i < W_FC1)  v = proj_w[i - W_PROJ];
    else if (i < W_FC2)  v = fc1_w[i - W_FC1];
    else                 v = fc2_w[i - W_FC2];
    out[i] = __float2bfloat16(v);
}

// ---------------------------------------------------------------------------
// Fused depthwise 3x3 conv (SAME) + residual + LayerNorm (bf16 LN output).
// ---------------------------------------------------------------------------
__global__ __launch_bounds__(Cdim)
void cpe_ln_kernel(const float* __restrict__ x,
                   const float* __restrict__ w,
                   const float* __restrict__ bias,
                   const float* __restrict__ lng,
                   const float* __restrict__ lnb,
                   float* __restrict__ y,
                   bf16* __restrict__ yln)
{
    int c = threadIdx.x;               // 0..383
    int n = blockIdx.x;                // 0..783
    int b = blockIdx.y;                // 0..31
    int i = n / 28, j = n % 28;

    const float* xb = x + (size_t)b * Ntok * Cdim + c;
    float acc = bias[c];
    const float* wc = w + c * 9;
#pragma unroll
    for (int di = -1; di <= 1; di++) {
        int ii = i + di;
        if (ii < 0 || ii >= 28) continue;
#pragma unroll
        for (int dj = -1; dj <= 1; dj++) {
            int jj = j + dj;
            if (jj < 0 || jj >= 28) continue;
            acc += wc[(di + 1) * 3 + (dj + 1)] * xb[(size_t)(ii * 28 + jj) * Cdim];
        }
    }
    size_t idx = ((size_t)b * Ntok + n) * Cdim + c;
    float val = x[idx] + acc;
    y[idx] = val;

    __shared__ float red[24];
    __shared__ float stats[2];
    float s = val, sq = val * val;
#pragma unroll
    for (int o = 16; o; o >>= 1) {
        s  += __shfl_xor_sync(0xffffffffu, s,  o);
        sq += __shfl_xor_sync(0xffffffffu, sq, o);
    }
    int warp = c >> 5, lane = c & 31;
    if (lane == 0) { red[warp] = s; red[12 + warp] = sq; }
    __syncthreads();
    if (c == 0) {
        float ts = 0.f, tq = 0.f;
#pragma unroll
        for (int k = 0; k < 12; k++) { ts += red[k]; tq += red[12 + k]; }
        float mean = ts * (1.f / Cdim);
        float var  = tq * (1.f / Cdim) - mean * mean;
        stats[0] = mean;
        stats[1] = rsqrtf(var + 1e-5f);
    }
    __syncthreads();
    float mean = stats[0], rs = stats[1];
    yln[idx] = __float2bfloat16((val - mean) * rs * lng[c] + lnb[c]);
}

// ---------------------------------------------------------------------------
// bf16 GEMM, NT form: C[m,n] = sum_k A[m,k] * W[n,k] (+ epilogue)
// BM=BN=128, BK=32, 256 threads (8 warps: 2m x 4n, warp tile 64x32).
// 2 CTAs/SM (128-reg cap). Single-buffer per-kk fragments to fit regs.
// EPI: 0 = none -> fp32 ; 2 = +bias + GELU -> bf16 ; 3 = +bias+res -> fp32
// ---------------------------------------------------------------------------
#define BM 128
#define BN 128
#define BK 32
#define STAGES 3
#define ASTG (BM * 64)                 // 8192 B per A stage (64B rows)
#define STG_BYTES (2 * ASTG)           // 16384 B (A + B)

__device__ __forceinline__ void cp16(unsigned saddr, const void* g)
{
    asm volatile("cp.async.cg.shared.global [%0], [%1], 16;\n" :: "r"(saddr), "l"(g));
}
__device__ __forceinline__ void ldsm4(uint32_t& r0, uint32_t& r1, uint32_t& r2,
                                      uint32_t& r3, uint32_t a)
{
    asm volatile("ldmatrix.sync.aligned.m8n8.x4.shared.b16 {%0,%1,%2,%3}, [%4];"
                 : "=r"(r0), "=r"(r1), "=r"(r2), "=r"(r3) : "r"(a));
}

template<int EPI, int K>
__global__ __launch_bounds__(256, 2)
void gemm_bf16(const bf16* __restrict__ A, const bf16* __restrict__ W,
               const float* __restrict__ bias, const float* __restrict__ res,
               void* __restrict__ Cout, int M, int N)
{
    __shared__ alignas(128) char sm[STAGES * STG_BYTES];   // 48 KB
    uint32_t sb = (uint32_t)__cvta_generic_to_shared(sm);

    int tid = threadIdx.x;
    int w = tid >> 5, l = tid & 31;
    int row0 = blockIdx.y * BM;
    int col0 = blockIdx.x * BN;
    int wm = (w & 1) * 64;
    int wn = (w >> 1) * 32;
    int g = l >> 2, t = l & 3;

    // --- ldmatrix address precompute ---
    int jj  = l >> 3;                 // matrix index within x4
    int rlo = l & 7;
    int rowA_in = (jj & 1) * 8 + rlo;
    int cA = jj >> 1;
    uint32_t aoff[4], axr[4];
#pragma unroll
    for (int mi = 0; mi < 4; mi++) {
        int rA = wm + mi * 16 + rowA_in;
        aoff[mi] = (uint32_t)rA * 64;
        axr[mi]  = (uint32_t)(((rA >> 1) & 3) << 4);
    }
    int rowB_in = (jj >> 1) * 8 + rlo;
    int cB = jj & 1;
    uint32_t boff[2], bxr[2];
#pragma unroll
    for (int p = 0; p < 2; p++) {
        int rB = wn + p * 16 + rowB_in;
        boff[p] = (uint32_t)(ASTG + rB * 64);
        bxr[p]  = (uint32_t)(((rB >> 1) & 3) << 4);
    }

    float acc[4][4][4];
#pragma unroll
    for (int mi = 0; mi < 4; mi++)
#pragma unroll
        for (int ni = 0; ni < 4; ni++)
#pragma unroll
            for (int r = 0; r < 4; r++) acc[mi][ni][r] = 0.f;

    constexpr int NS = K / BK;

    // loader: 512 16B chunks per matrix per stage; 2 per thread per matrix
    auto load_stage = [&](int s) {
        uint32_t tb = sb + (s % STAGES) * STG_BYTES;
        int kt = s * BK;
        const bf16* Ab = A + (size_t)row0 * K + kt;
        const bf16* Wb = W + (size_t)col0 * K + kt;
#pragma unroll
        for (int i = 0; i < 2; i++) {
            int id = tid + i * 256;        // 0..511
            int r = id >> 2, c = id & 3;
            int cs = c ^ ((r >> 1) & 3);
            cp16(tb + r * 64 + cs * 16, Ab + (size_t)r * K + c * 8);
            cp16(tb + ASTG + r * 64 + cs * 16, Wb + (size_t)r * K + c * 8);
        }
    };

    load_stage(0);
    asm volatile("cp.async.commit_group;\n");
    load_stage(1);
    asm volatile("cp.async.commit_group;\n");

#pragma unroll
    for (int s = 0; s < NS; s++) {
        asm volatile("cp.async.wait_group 1;\n");
        __syncthreads();

        if (s + STAGES - 1 < NS) load_stage(s + STAGES - 1);
        asm volatile("cp.async.commit_group;\n");   // unconditional: keeps count

        uint32_t stb = sb + (s % STAGES) * STG_BYTES;
#pragma unroll
        for (int kk = 0; kk < 2; kk++) {
            uint32_t c0 = kk * 2;       // 16B chunk base within 64B row
            uint32_t af[4][4], bq[2][4];
#pragma unroll
            for (int mi = 0; mi < 4; mi++)
                ldsm4(af[mi][0], af[mi][1], af[mi][2], af[mi][3],
                      stb + aoff[mi] + ((((c0 + cA) << 4)) ^ axr[mi]));
#pragma unroll
            for (int p = 0; p < 2; p++)
                ldsm4(bq[p][0], bq[p][1], bq[p][2], bq[p][3],
                      stb + boff[p] + ((((c0 + cB) << 4)) ^ bxr[p]));

#pragma unroll
            for (int mi = 0; mi < 4; mi++)
#pragma unroll
                for (int ni = 0; ni < 4; ni++) {
                    int p = ni >> 1, q = ni & 1;
                    asm volatile(
                        "mma.sync.aligned.m16n8k16.row.col.f32.bf16.bf16.f32 "
                        "{%0,%1,%2,%3}, {%4,%5,%6,%7}, {%8,%9}, {%0,%1,%2,%3};"
                        : "+f"(acc[mi][ni][0]), "+f"(acc[mi][ni][1]),
                          "+f"(acc[mi][ni][2]), "+f"(acc[mi][ni][3])
                        : "r"(af[mi][0]), "r"(af[mi][1]), "r"(af[mi][2]), "r"(af[mi][3]),
                          "r"(bq[p][2 * q]), "r"(bq[p][2 * q + 1]));
                }
        }
    }

    // ---- epilogue: float2 / bfloat162 stores (cols 2t,2t+1 adjacent) ----
#pragma unroll
    for (int mi = 0; mi < 4; mi++) {
#pragma unroll
        for (int ni = 0; ni < 4; ni++) {
            int col = col0 + wn + ni * 8 + 2 * t;
#pragma unroll
            for (int half = 0; half < 2; half++) {
                int row = row0 + wm + mi * 16 + g + half * 8;
                size_t idx = (size_t)row * N + col;
                float v0 = acc[mi][ni][2 * half];
                float v1 = acc[mi][ni][2 * half + 1];
                if (EPI == 0) {
                    *(float2*)&((float*)Cout)[idx] = make_float2(v0, v1);
                } else if (EPI == 2) {
                    float2 bv = *(const float2*)&bias[col];
                    v0 += bv.x; v1 += bv.y;
                    v0 = 0.5f * v0 * (1.f + erff(v0 * 0.7071067811865475f));
                    v1 = 0.5f * v1 * (1.f + erff(v1 * 0.7071067811865475f));
                    __nv_bfloat162 pk;
                    pk.x = __float2bfloat16(v0);
                    pk.y = __float2bfloat16(v1);
                    *(__nv_bfloat162*)&((bf16*)Cout)[idx] = pk;
                } else {
                    float2 bv = *(const float2*)&bias[col];
                    float2 rv = *(const float2*)&res[idx];
                    v0 += bv.x + rv.x; v1 += bv.y + rv.y;
                    *(float2*)&((float*)Cout)[idx] = make_float2(v0, v1);
                }
            }
        }
    }
}

// ---------------------------------------------------------------------------
// Channel attention stage A (partial): accumulate (k*s)^T v into raw logits.
// ---------------------------------------------------------------------------
__global__ __launch_bounds__(256)
void attnA_partial(const float* __restrict__ qkv, float* __restrict__ raw)
{
    __shared__ float ks[32][49];
    __shared__ float vs[32][49];

    int bh = blockIdx.x;
    int b = bh >> 3, h = bh & 7;
    int nstart = blockIdx.y * 112;
    int nend   = nstart + 112;
    int tid = threadIdx.x;
    int tx = tid & 15, ty = tid >> 4;
    const float scale = 0.14433756729740643f;   // 48^-0.5

    float acc[3][3] = {{0.f,0.f,0.f},{0.f,0.f,0.f},{0.f,0.f,0.f}};
    const float* base = qkv + (size_t)b * Ntok * H3 + h * HD;

    for (int n0 = nstart; n0 < nend; n0 += 32) {
        int cnt = min(32, nend - n0);
        for (int idx = tid; idx < cnt * HD; idx += 256) {
            int nn = idx / HD, d = idx % HD;
            const float* r = base + (size_t)(n0 + nn) * H3;
            ks[nn][d] = r[Cdim + d] * scale;   // k
            vs[nn][d] = r[2 * Cdim + d];       // v
        }
        __syncthreads();
        for (int nn = 0; nn < cnt; nn++) {
            float rk[3], rv[3];
#pragma unroll
            for (int i = 0; i < 3; i++) { rk[i] = ks[nn][ty * 3 + i]; rv[i] = vs[nn][tx * 3 + i]; }
#pragma unroll
            for (int i = 0; i < 3; i++)
#pragma unroll
                for (int j = 0; j < 3; j++)
                    acc[i][j] = fmaf(rk[i], rv[j], acc[i][j]);
        }
        __syncthreads();
    }

    float* o = raw + (size_t)bh * (HD * HD);
#pragma unroll
    for (int i = 0; i < 3; i++)
#pragma unroll
        for (int j = 0; j < 3; j++)
            atomicAdd(&o[(ty * 3 + i) * HD + tx * 3 + j], acc[i][j]);
}

// softmax over last dim of 48x48 logits; one thread per (bh, d) row.
__global__ __launch_bounds__(256)
void attnA_softmax(const float* __restrict__ raw, float* __restrict__ attn_out)
{
    int idx = blockIdx.x * 256 + threadIdx.x;
    if (idx >= Bsz * NH * HD) return;
    const float* r = raw + (size_t)idx * HD;
    float* o = attn_out + (size_t)idx * HD;
    float m = -1e30f;
#pragma unroll
    for (int e = 0; e < HD; e++) m = fmaxf(m, r[e]);
    float s = 0.f;
    float tv[HD];
#pragma unroll
    for (int e = 0; e < HD; e++) { tv[e] = expf(r[e] - m); s += tv[e]; }
    float inv = 1.f / s;
#pragma unroll
    for (int e = 0; e < HD; e++) o[e] = tv[e] * inv;
}

// ---------------------------------------------------------------------------
// Channel attention stage B: out[b,n,h*48+d] = sum_e attn[d,e] * q[b,n,h,e]
// ---------------------------------------------------------------------------
__global__ __launch_bounds__(384)
void attnB_kernel(const float* __restrict__ qkv, const float* __restrict__ attn,
                  bf16* __restrict__ out)
{
    __shared__ float at[48 * 49];
    __shared__ float qs[8][48];

    int bh = blockIdx.x;
    int b = bh >> 3, h = bh & 7;
    int n0 = blockIdx.y * 8;
    int tid = threadIdx.x;

    const float* ab = attn + (size_t)bh * (HD * HD);
    for (int idx = tid; idx < HD * HD; idx += 384) {
        int d = idx / HD, e = idx % HD;
        at[d * 49 + e] = ab[idx];
    }
    int nl = tid / HD;
    int d  = tid % HD;
    qs[nl][d] = qkv[((size_t)b * Ntok + n0 + nl) * H3 + h * HD + d];  // q
    __syncthreads();

    float acc = 0.f;
#pragma unroll
    for (int e = 0; e < HD; e++)
        acc = fmaf(at[d * 49 + e], qs[nl][e], acc);

    out[((size_t)b * Ntok + n0 + nl) * Cdim + h * HD + d] = __float2bfloat16(acc);
}

// ---------------------------------------------------------------------------
// Launch
// ---------------------------------------------------------------------------
extern "C" void kernel_launch(void* const* d_in, const int* in_sizes, int n_in,
                              void* d_out, int out_size)
{
    const float* x       = (const float*)d_in[0];
    const float* cpe0_w  = (const float*)d_in[3];
    const float* cpe0_b  = (const float*)d_in[4];
    const float* cpe1_w  = (const float*)d_in[5];
    const float* cpe1_b  = (const float*)d_in[6];
    const float* norm1_g = (const float*)d_in[7];
    const float* norm1_b = (const float*)d_in[8];
    const float* qkv_w   = (const float*)d_in[9];
    const float* proj_w  = (const float*)d_in[10];
    const float* proj_b  = (const float*)d_in[11];
    const float* norm2_g = (const float*)d_in[12];
    const float* norm2_b = (const float*)d_in[13];
    const float* fc1_w   = (const float*)d_in[14];
    const float* fc1_b   = (const float*)d_in[15];
    const float* fc2_w   = (const float*)d_in[16];
    const float* fc2_b   = (const float*)d_in[17];
    float* out = (float*)d_out;

    float *xa, *qkvb, *attn, *attn2, *xb;
    bf16 *ln, *att, *hbuf, *wbf;
    cudaGetSymbolAddress((void**)&xa,    g_xa);
    cudaGetSymbolAddress((void**)&ln,    g_ln);
    cudaGetSymbolAddress((void**)&qkvb,  g_qkv);
    cudaGetSymbolAddress((void**)&attn,  g_attn);
    cudaGetSymbolAddress((void**)&attn2, g_attn2);
    cudaGetSymbolAddress((void**)&att,   g_att);
    cudaGetSymbolAddress((void**)&xb,    g_xb);
    cudaGetSymbolAddress((void**)&hbuf,  g_h);
    cudaGetSymbolAddress((void**)&wbf,   g_wbf);

    dim3 cpeGrid(Ntok, Bsz);

    // one launch: convert all weights to bf16
    cvt_all_kernel<<<(W_TOT + 255) / 256, 256>>>(qkv_w, proj_w, fc1_w, fc2_w, wbf);

    // zero raw attention logits
    cudaMemsetAsync(attn, 0, (size_t)Bsz * NH * HD * HD * sizeof(float));

    // xa = cpe0(x); ln = LN1(xa) [bf16]
    cpe_ln_kernel<<<cpeGrid, Cdim>>>(x, cpe0_w, cpe0_b, norm1_g, norm1_b, xa, ln);
    // qkv = ln1 @ qkv_w^T  (fp32 out)
    gemm_bf16<0, Cdim><<<dim3(H3 / BN, NT / BM), 256>>>(ln, wbf + W_QKV, nullptr, nullptr, qkvb, NT, H3);
    // channel attention
    attnA_partial<<<dim3(Bsz * NH, 7), 256>>>(qkvb, attn);
    attnA_softmax<<<(Bsz * NH * HD + 255) / 256, 256>>>(attn, attn2);
    attnB_kernel<<<dim3(Bsz * NH, Ntok / 8), 384>>>(qkvb, attn2, att);
    // xb = xa + att @ proj_w^T + proj_b  (fp32 out)
    gemm_bf16<3, Cdim><<<dim3(Cdim / BN, NT / BM), 256>>>(att, wbf + W_PROJ, proj_b, xa, xb, NT, Cdim);
    // xc = cpe1(xb) -> xa ; ln = LN2(xc) [bf16]
    cpe_ln_kernel<<<cpeGrid, Cdim>>>(xb, cpe1_w, cpe1_b, norm2_g, norm2_b, xa, ln);
    // h = gelu(ln2 @ fc1^T + b1) [bf16 out]
    gemm_bf16<2, Cdim><<<dim3(HID / BN, NT / BM), 256>>>(ln, wbf + W_FC1, fc1_b, nullptr, hbuf, NT, HID);
    // out = xc + h @ fc2^T + b2 (fp32 out)
    gemm_bf16<3, HID><<<dim3(Cdim / BN, NT / BM), 256>>>(hbuf, wbf + W_FC2, fc2_b, xa, out, NT, Cdim);
}

// round 8
// speedup vs baseline: 4.4690x; 1.0670x over previous
#include <cuda_runtime.h>
#include <cuda_bf16.h>
#include <math.h>
#include <stdint.h>

// ---------------------------------------------------------------------------
// ChannelBlock: B=32, N=784 (28x28), C=384, heads=8, hd=48, MLP hidden=1536
// bf16 mma.sync GEMMs (R7 config) + tiled cpe_ln + unrolled no-atomic attnA.
// ---------------------------------------------------------------------------

#define Bsz   32
#define Ntok  784
#define Cdim  384
#define NT    (Bsz * Ntok)     // 25088
#define H3    (3 * Cdim)       // 1152
#define HID   1536
#define NH    8
#define HD    48
#define NCHUNK 7               // attnA token chunks (112 each)

typedef __nv_bfloat16 bf16;

// scratch (static device memory; no allocation anywhere)
__device__ float g_xa  [(size_t)NT * Cdim];
__device__ bf16  g_ln  [(size_t)NT * Cdim];
__device__ float g_qkv [(size_t)NT * H3];
__device__ float g_attn[(size_t)NCHUNK * Bsz * NH * HD * HD];  // partial logits
__device__ float g_attn2[(size_t)Bsz * NH * HD * HD];          // softmaxed
__device__ bf16  g_att [(size_t)NT * Cdim];
__device__ float g_xb  [(size_t)NT * Cdim];
__device__ bf16  g_h   [(size_t)NT * HID];
// bf16 weights: qkv | proj | fc1 | fc2
#define W_QKV 0
#define W_PROJ (H3 * Cdim)
#define W_FC1  (W_PROJ + Cdim * Cdim)
#define W_FC2  (W_FC1 + HID * Cdim)
#define W_TOT  (W_FC2 + Cdim * HID)
__device__ bf16  g_wbf [(size_t)W_TOT];

// single launch: convert all 4 weight matrices to bf16
__global__ void cvt_all_kernel(const float* __restrict__ qkv_w,
                               const float* __restrict__ proj_w,
                               const float* __restrict__ fc1_w,
                               const float* __restrict__ fc2_w,
                               bf16* __restrict__ out)
{
    int i = blockIdx.x * blockDim.x + threadIdx.x;
    if (i >= W_TOT) return;
    float v;
    if (i < W_PROJ)      v = qkv_w[i];
    else if (i < W_FC1)  v = proj_w[i - W_PROJ];
    else if (i < W_FC2)  v = fc1_w[i - W_FC1];
    else                 v = fc2_w[i - W_FC2];
    out[i] = __float2bfloat16(v);
}

// ---------------------------------------------------------------------------
// Tiled fused cpe + LN. Block = (b, row i, 7-token group) x 384 channels.
// smem halo tile (3 rows x 9 cols x 384 ch) -> 2.3x less L2 read traffic.
// ---------------------------------------------------------------------------
#define TJ 7
__global__ __launch_bounds__(Cdim)
void cpe_ln_kernel(const float* __restrict__ x,
                   const float* __restrict__ w,
                   const float* __restrict__ bias,
                   const float* __restrict__ lng,
                   const float* __restrict__ lnb,
                   float* __restrict__ y,
                   bf16* __restrict__ yln)
{
    __shared__ float tile[3][TJ + 2][Cdim];
    __shared__ float redS[12][TJ], redQ[12][TJ];
    __shared__ float stats[TJ][2];

    int c  = threadIdx.x;              // channel 0..383
    int jg = blockIdx.x;               // 0..3
    int i  = blockIdx.y;               // 0..27
    int b  = blockIdx.z;               // 0..31
    int j0 = jg * TJ;

    const float* xb = x + (size_t)b * Ntok * Cdim;

    // load 3 x 9 token slots (zero-padded halo), coalesced per slot
#pragma unroll
    for (int s = 0; s < 3 * (TJ + 2); s++) {
        int ri = s / (TJ + 2) + i - 1;
        int cj = s % (TJ + 2) + j0 - 1;
        float v = 0.f;
        if (ri >= 0 && ri < 28 && cj >= 0 && cj < 28)
            v = xb[(size_t)(ri * 28 + cj) * Cdim + c];
        tile[s / (TJ + 2)][s % (TJ + 2)][c] = v;
    }
    __syncthreads();

    const float* wc = w + c * 9;
    float wr[9];
#pragma unroll
    for (int q = 0; q < 9; q++) wr[q] = wc[q];
    float bs = bias[c];

    float val[TJ];
#pragma unroll
    for (int jt = 0; jt < TJ; jt++) {
        float acc = bs;
#pragma unroll
        for (int di = 0; di < 3; di++)
#pragma unroll
            for (int dj = 0; dj < 3; dj++)
                acc += wr[di * 3 + dj] * tile[di][jt + dj][c];
        val[jt] = tile[1][1 + jt][c] + acc;
    }

    // per-token LN reductions over 384 channels
    int warp = c >> 5, lane = c & 31;
#pragma unroll
    for (int jt = 0; jt < TJ; jt++) {
        float s = val[jt], q = val[jt] * val[jt];
#pragma unroll
        for (int o = 16; o; o >>= 1) {
            s += __shfl_xor_sync(0xffffffffu, s, o);
            q += __shfl_xor_sync(0xffffffffu, q, o);
        }
        if (lane == 0) { redS[warp][jt] = s; redQ[warp][jt] = q; }
    }
    __syncthreads();
    if (c < TJ) {
        float ts = 0.f, tq = 0.f;
#pragma unroll
        for (int k = 0; k < 12; k++) { ts += redS[k][c]; tq += redQ[k][c]; }
        float mean = ts * (1.f / Cdim);
        float var  = tq * (1.f / Cdim) - mean * mean;
        stats[c][0] = mean;
        stats[c][1] = rsqrtf(var + 1e-5f);
    }
    __syncthreads();

    float gg = lng[c], bb = lnb[c];
#pragma unroll
    for (int jt = 0; jt < TJ; jt++) {
        size_t idx = ((size_t)b * Ntok + i * 28 + j0 + jt) * Cdim + c;
        float v = val[jt];
        y[idx] = v;
        yln[idx] = __float2bfloat16((v - stats[jt][0]) * stats[jt][1] * gg + bb);
    }
}

// ---------------------------------------------------------------------------
// bf16 GEMM (unchanged from R7)
// ---------------------------------------------------------------------------
#define BM 128
#define BN 128
#define BK 32
#define STAGES 3
#define ASTG (BM * 64)
#define STG_BYTES (2 * ASTG)

__device__ __forceinline__ void cp16(unsigned saddr, const void* g)
{
    asm volatile("cp.async.cg.shared.global [%0], [%1], 16;\n" :: "r"(saddr), "l"(g));
}
__device__ __forceinline__ void ldsm4(uint32_t& r0, uint32_t& r1, uint32_t& r2,
                                      uint32_t& r3, uint32_t a)
{
    asm volatile("ldmatrix.sync.aligned.m8n8.x4.shared.b16 {%0,%1,%2,%3}, [%4];"
                 : "=r"(r0), "=r"(r1), "=r"(r2), "=r"(r3) : "r"(a));
}

template<int EPI, int K>
__global__ __launch_bounds__(256, 2)
void gemm_bf16(const bf16* __restrict__ A, const bf16* __restrict__ W,
               const float* __restrict__ bias, const float* __restrict__ res,
               void* __restrict__ Cout, int M, int N)
{
    __shared__ alignas(128) char sm[STAGES * STG_BYTES];
    uint32_t sb = (uint32_t)__cvta_generic_to_shared(sm);

    int tid = threadIdx.x;
    int w = tid >> 5, l = tid & 31;
    int row0 = blockIdx.y * BM;
    int col0 = blockIdx.x * BN;
    int wm = (w & 1) * 64;
    int wn = (w >> 1) * 32;
    int g = l >> 2, t = l & 3;

    int jj  = l >> 3;
    int rlo = l & 7;
    int rowA_in = (jj & 1) * 8 + rlo;
    int cA = jj >> 1;
    uint32_t aoff[4], axr[4];
#pragma unroll
    for (int mi = 0; mi < 4; mi++) {
        int rA = wm + mi * 16 + rowA_in;
        aoff[mi] = (uint32_t)rA * 64;
        axr[mi]  = (uint32_t)(((rA >> 1) & 3) << 4);
    }
    int rowB_in = (jj >> 1) * 8 + rlo;
    int cB = jj & 1;
    uint32_t boff[2], bxr[2];
#pragma unroll
    for (int p = 0; p < 2; p++) {
        int rB = wn + p * 16 + rowB_in;
        boff[p] = (uint32_t)(ASTG + rB * 64);
        bxr[p]  = (uint32_t)(((rB >> 1) & 3) << 4);
    }

    float acc[4][4][4];
#pragma unroll
    for (int mi = 0; mi < 4; mi++)
#pragma unroll
        for (int ni = 0; ni < 4; ni++)
#pragma unroll
            for (int r = 0; r < 4; r++) acc[mi][ni][r] = 0.f;

    constexpr int NS = K / BK;

    auto load_stage = [&](int s) {
        uint32_t tb = sb + (s % STAGES) * STG_BYTES;
        int kt = s * BK;
        const bf16* Ab = A + (size_t)row0 * K + kt;
        const bf16* Wb = W + (size_t)col0 * K + kt;
#pragma unroll
        for (int i = 0; i < 2; i++) {
            int id = tid + i * 256;
            int r = id >> 2, c = id & 3;
            int cs = c ^ ((r >> 1) & 3);
            cp16(tb + r * 64 + cs * 16, Ab + (size_t)r * K + c * 8);
            cp16(tb + ASTG + r * 64 + cs * 16, Wb + (size_t)r * K + c * 8);
        }
    };

    load_stage(0);
    asm volatile("cp.async.commit_group;\n");
    load_stage(1);
    asm volatile("cp.async.commit_group;\n");

#pragma unroll
    for (int s = 0; s < NS; s++) {
        asm volatile("cp.async.wait_group 1;\n");
        __syncthreads();

        if (s + STAGES - 1 < NS) load_stage(s + STAGES - 1);
        asm volatile("cp.async.commit_group;\n");

        uint32_t stb = sb + (s % STAGES) * STG_BYTES;
#pragma unroll
        for (int kk = 0; kk < 2; kk++) {
            uint32_t c0 = kk * 2;
            uint32_t af[4][4], bq[2][4];
#pragma unroll
            for (int mi = 0; mi < 4; mi++)
                ldsm4(af[mi][0], af[mi][1], af[mi][2], af[mi][3],
                      stb + aoff[mi] + ((((c0 + cA) << 4)) ^ axr[mi]));
#pragma unroll
            for (int p = 0; p < 2; p++)
                ldsm4(bq[p][0], bq[p][1], bq[p][2], bq[p][3],
                      stb + boff[p] + ((((c0 + cB) << 4)) ^ bxr[p]));

#pragma unroll
            for (int mi = 0; mi < 4; mi++)
#pragma unroll
                for (int ni = 0; ni < 4; ni++) {
                    int p = ni >> 1, q = ni & 1;
                    asm volatile(
                        "mma.sync.aligned.m16n8k16.row.col.f32.bf16.bf16.f32 "
                        "{%0,%1,%2,%3}, {%4,%5,%6,%7}, {%8,%9}, {%0,%1,%2,%3};"
                        : "+f"(acc[mi][ni][0]), "+f"(acc[mi][ni][1]),
                          "+f"(acc[mi][ni][2]), "+f"(acc[mi][ni][3])
                        : "r"(af[mi][0]), "r"(af[mi][1]), "r"(af[mi][2]), "r"(af[mi][3]),
                          "r"(bq[p][2 * q]), "r"(bq[p][2 * q + 1]));
                }
        }
    }

#pragma unroll
    for (int mi = 0; mi < 4; mi++) {
#pragma unroll
        for (int ni = 0; ni < 4; ni++) {
            int col = col0 + wn + ni * 8 + 2 * t;
#pragma unroll
            for (int half = 0; half < 2; half++) {
                int row = row0 + wm + mi * 16 + g + half * 8;
                size_t idx = (size_t)row * N + col;
                float v0 = acc[mi][ni][2 * half];
                float v1 = acc[mi][ni][2 * half + 1];
                if (EPI == 0) {
                    *(float2*)&((float*)Cout)[idx] = make_float2(v0, v1);
                } else if (EPI == 2) {
                    float2 bv = *(const float2*)&bias[col];
                    v0 += bv.x; v1 += bv.y;
                    v0 = 0.5f * v0 * (1.f + erff(v0 * 0.7071067811865475f));
                    v1 = 0.5f * v1 * (1.f + erff(v1 * 0.7071067811865475f));
                    __nv_bfloat162 pk;
                    pk.x = __float2bfloat16(v0);
                    pk.y = __float2bfloat16(v1);
                    *(__nv_bfloat162*)&((bf16*)Cout)[idx] = pk;
                } else {
                    float2 bv = *(const float2*)&bias[col];
                    float2 rv = *(const float2*)&res[idx];
                    v0 += bv.x + rv.x; v1 += bv.y + rv.y;
                    *(float2*)&((float*)Cout)[idx] = make_float2(v0, v1);
                }
            }
        }
    }
}

// ---------------------------------------------------------------------------
// Channel attention stage A: per (bh, chunk) block computes partial (k*s)^T v
// over 112 tokens, fully-unrolled 16-token sub-chunks, plain stores (no atomics).
// ---------------------------------------------------------------------------
__global__ __launch_bounds__(256)
void attnA_partial(const float* __restrict__ qkv, float* __restrict__ partial)
{
    __shared__ float ks[16][49];
    __shared__ float vs[16][49];

    int bh = blockIdx.x;
    int b = bh >> 3, h = bh & 7;
    int chunk = blockIdx.y;            // 0..6
    int nstart = chunk * 112;
    int tid = threadIdx.x;
    int tx = tid & 15, ty = tid >> 4;
    const float scale = 0.14433756729740643f;   // 48^-0.5

    float acc[3][3] = {{0.f,0.f,0.f},{0.f,0.f,0.f},{0.f,0.f,0.f}};
    const float* base = qkv + (size_t)b * Ntok * H3 + h * HD;

    for (int n0 = nstart; n0 < nstart + 112; n0 += 16) {
        // load 16 tokens x 48 d for k and v: 768 = 3 x 256
#pragma unroll
        for (int it = 0; it < 3; it++) {
            int idx = tid + it * 256;
            int nn = idx / HD, d = idx - nn * HD;
            const float* r = base + (size_t)(n0 + nn) * H3;
            ks[nn][d] = r[Cdim + d] * scale;
            vs[nn][d] = r[2 * Cdim + d];
        }
        __syncthreads();
#pragma unroll
        for (int nn = 0; nn < 16; nn++) {
            float rk[3], rv[3];
#pragma unroll
            for (int i = 0; i < 3; i++) { rk[i] = ks[nn][ty * 3 + i]; rv[i] = vs[nn][tx * 3 + i]; }
#pragma unroll
            for (int i = 0; i < 3; i++)
#pragma unroll
                for (int j = 0; j < 3; j++)
                    acc[i][j] = fmaf(rk[i], rv[j], acc[i][j]);
        }
        __syncthreads();
    }

    float* o = partial + ((size_t)chunk * (Bsz * NH) + bh) * (HD * HD);
#pragma unroll
    for (int i = 0; i < 3; i++)
#pragma unroll
        for (int j = 0; j < 3; j++)
            o[(ty * 3 + i) * HD + tx * 3 + j] = acc[i][j];
}

// softmax over last dim of 48x48 logits after summing 7 partials.
__global__ __launch_bounds__(256)
void attnA_softmax(const float* __restrict__ partial, float* __restrict__ attn_out)
{
    int idx = blockIdx.x * 256 + threadIdx.x;     // bh*48 + d
    if (idx >= Bsz * NH * HD) return;
    int bh = idx / HD, d = idx - bh * HD;

    float row[HD];
#pragma unroll
    for (int e = 0; e < HD; e++) row[e] = 0.f;
#pragma unroll
    for (int ch = 0; ch < NCHUNK; ch++) {
        const float* p = partial + ((size_t)ch * (Bsz * NH) + bh) * (HD * HD) + d * HD;
#pragma unroll
        for (int e = 0; e < HD; e++) row[e] += p[e];
    }
    float m = -1e30f;
#pragma unroll
    for (int e = 0; e < HD; e++) m = fmaxf(m, row[e]);
    float s = 0.f;
#pragma unroll
    for (int e = 0; e < HD; e++) { row[e] = expf(row[e] - m); s += row[e]; }
    float inv = 1.f / s;
    float* o = attn_out + (size_t)bh * (HD * HD) + d * HD;
#pragma unroll
    for (int e = 0; e < HD; e++) o[e] = row[e] * inv;
}

// ---------------------------------------------------------------------------
// Channel attention stage B: out[b,n,h*48+d] = sum_e attn[d,e] * q[b,n,h,e]
// ---------------------------------------------------------------------------
__global__ __launch_bounds__(384)
void attnB_kernel(const float* __restrict__ qkv, const float* __restrict__ attn,
                  bf16* __restrict__ out)
{
    __shared__ float at[48 * 49];
    __shared__ float qs[8][48];

    int bh = blockIdx.x;
    int b = bh >> 3, h = bh & 7;
    int n0 = blockIdx.y * 8;
    int tid = threadIdx.x;

    const float* ab = attn + (size_t)bh * (HD * HD);
    for (int idx = tid; idx < HD * HD; idx += 384) {
        int d = idx / HD, e = idx % HD;
        at[d * 49 + e] = ab[idx];
    }
    int nl = tid / HD;
    int d  = tid % HD;
    qs[nl][d] = qkv[((size_t)b * Ntok + n0 + nl) * H3 + h * HD + d];
    __syncthreads();

    float acc = 0.f;
#pragma unroll
    for (int e = 0; e < HD; e++)
        acc = fmaf(at[d * 49 + e], qs[nl][e], acc);

    out[((size_t)b * Ntok + n0 + nl) * Cdim + h * HD + d] = __float2bfloat16(acc);
}

// ---------------------------------------------------------------------------
// Launch
// ---------------------------------------------------------------------------
extern "C" void kernel_launch(void* const* d_in, const int* in_sizes, int n_in,
                              void* d_out, int out_size)
{
    const float* x       = (const float*)d_in[0];
    const float* cpe0_w  = (const float*)d_in[3];
    const float* cpe0_b  = (const float*)d_in[4];
    const float* cpe1_w  = (const float*)d_in[5];
    const float* cpe1_b  = (const float*)d_in[6];
    const float* norm1_g = (const float*)d_in[7];
    const float* norm1_b = (const float*)d_in[8];
    const float* qkv_w   = (const float*)d_in[9];
    const float* proj_w  = (const float*)d_in[10];
    const float* proj_b  = (const float*)d_in[11];
    const float* norm2_g = (const float*)d_in[12];
    const float* norm2_b = (const float*)d_in[13];
    const float* fc1_w   = (const float*)d_in[14];
    const float* fc1_b   = (const float*)d_in[15];
    const float* fc2_w   = (const float*)d_in[16];
    const float* fc2_b   = (const float*)d_in[17];
    float* out = (float*)d_out;

    float *xa, *qkvb, *attn, *attn2, *xb;
    bf16 *ln, *att, *hbuf, *wbf;
    cudaGetSymbolAddress((void**)&xa,    g_xa);
    cudaGetSymbolAddress((void**)&ln,    g_ln);
    cudaGetSymbolAddress((void**)&qkvb,  g_qkv);
    cudaGetSymbolAddress((void**)&attn,  g_attn);
    cudaGetSymbolAddress((void**)&attn2, g_attn2);
    cudaGetSymbolAddress((void**)&att,   g_att);
    cudaGetSymbolAddress((void**)&xb,    g_xb);
    cudaGetSymbolAddress((void**)&hbuf,  g_h);
    cudaGetSymbolAddress((void**)&wbf,   g_wbf);

    dim3 cpeGrid(4, 28, Bsz);   // 7-token groups x rows x batch

    // one launch: convert all weights to bf16
    cvt_all_kernel<<<(W_TOT + 255) / 256, 256>>>(qkv_w, proj_w, fc1_w, fc2_w, wbf);

    // xa = cpe0(x); ln = LN1(xa) [bf16]
    cpe_ln_kernel<<<cpeGrid, Cdim>>>(x, cpe0_w, cpe0_b, norm1_g, norm1_b, xa, ln);
    // qkv = ln1 @ qkv_w^T  (fp32 out)
    gemm_bf16<0, Cdim><<<dim3(H3 / BN, NT / BM), 256>>>(ln, wbf + W_QKV, nullptr, nullptr, qkvb, NT, H3);
    // channel attention
    attnA_partial<<<dim3(Bsz * NH, NCHUNK), 256>>>(qkvb, attn);
    attnA_softmax<<<(Bsz * NH * HD + 255) / 256, 256>>>(attn, attn2);
    attnB_kernel<<<dim3(Bsz * NH, Ntok / 8), 384>>>(qkvb, attn2, att);
    // xb = xa + att @ proj_w^T + proj_b  (fp32 out)
    gemm_bf16<3, Cdim><<<dim3(Cdim / BN, NT / BM), 256>>>(att, wbf + W_PROJ, proj_b, xa, xb, NT, Cdim);
    // xc = cpe1(xb) -> xa ; ln = LN2(xc) [bf16]
    cpe_ln_kernel<<<cpeGrid, Cdim>>>(xb, cpe1_w, cpe1_b, norm2_g, norm2_b, xa, ln);
    // h = gelu(ln2 @ fc1^T + b1) [bf16 out]
    gemm_bf16<2, Cdim><<<dim3(HID / BN, NT / BM), 256>>>(ln, wbf + W_FC1, fc1_b, nullptr, hbuf, NT, HID);
    // out = xc + h @ fc2^T + b2 (fp32 out)
    gemm_bf16<3, HID><<<dim3(Cdim / BN, NT / BM), 256>>>(hbuf, wbf + W_FC2, fc2_b, xa, out, NT, Cdim);
}